// round 6
// baseline (speedup 1.0000x reference)
#include <cuda_runtime.h>
#include <cuda_fp16.h>
#include <cstdint>
#include <math.h>

#define SEQ 2048
#define DIM 2048
#define NH 16
#define HD 192
#define NOPE 128
#define ROPE 64
#define VD 128
#define QKLD (NH*HD)   // 3072

// ---------------------------------------------------------------------------
// scratch (allocation-free __device__ globals)
// ---------------------------------------------------------------------------
__device__ __half g_xh [SEQ*DIM],   g_xl [SEQ*DIM];
__device__ __half g_wqh[QKLD*DIM];
__device__ __half g_wkh[QKLD*DIM];
__device__ __half g_wvh[DIM*DIM];
__device__ __half g_woh[DIM*DIM];
__device__ __half g_qh [SEQ*QKLD],  g_ql [SEQ*QKLD];
__device__ __half g_kh [SEQ*QKLD],  g_kl [SEQ*QKLD];
__device__ __half g_vh [SEQ*DIM],   g_vl [SEQ*DIM];
__device__ __half g_vth[DIM*SEQ],   g_vtl[DIM*SEQ];
__device__ float  g_s[(long long)NH*SEQ*SEQ];
__device__ __half g_p[(long long)NH*SEQ*SEQ];
__device__ __half g_oh [SEQ*DIM],   g_ol [SEQ*DIM];

// ---------------------------------------------------------------------------
static __device__ __forceinline__ uint32_t s2u(const void* p) {
    uint32_t a;
    asm("{ .reg .u64 t; cvta.to.shared.u64 t, %1; cvt.u32.u64 %0, t; }" : "=r"(a) : "l"(p));
    return a;
}
#define CPA16(dst, src) \
    asm volatile("cp.async.cg.shared.global [%0], [%1], 16;" :: "r"(dst), "l"(src))
#define CPCOMMIT() asm volatile("cp.async.commit_group;" ::: "memory")
#define CPWAIT2()  asm volatile("cp.async.wait_group 2;" ::: "memory")

#define LDMX4(r0, r1, r2, r3, a) \
    asm volatile("ldmatrix.sync.aligned.m8n8.x4.shared.b16 {%0,%1,%2,%3}, [%4];" \
                 : "=r"(r0), "=r"(r1), "=r"(r2), "=r"(r3) : "r"(a))

#define MMA16816(d, a, b) \
    asm volatile("mma.sync.aligned.m16n8k16.row.col.f32.f16.f16.f32 " \
                 "{%0,%1,%2,%3},{%4,%5,%6,%7},{%8,%9},{%0,%1,%2,%3};" \
                 : "+f"((d)[0]), "+f"((d)[1]), "+f"((d)[2]), "+f"((d)[3]) \
                 : "r"((a)[0]), "r"((a)[1]), "r"((a)[2]), "r"((a)[3]), \
                   "r"((b)[0]), "r"((b)[1]))

// ---------------------------------------------------------------------------
// HMMA GEMM:  C = A * B^T  (both operands K-major), 2-term split numerics.
//   acc = Ah*Bh^T  [+ Al*Bh^T if ASPL]  [+ Ah*Bl^T if BSPL]
//   Tile MT x NT (MT*NT = 32768), 512 threads, warp tile 32x64,
//   4-stage cp.async pipeline, K-stage 32.
//   CSKIP: skip blocks fully above diagonal.  KLIM: k < m0+MT.
//   CHALF: write split-fp16 (Ch,Cl) else fp32.
// ---------------------------------------------------------------------------
template<int MT, int NT, bool ASPL, bool BSPL, bool CSKIP, bool KLIM, bool CHALF>
__global__ void __launch_bounds__(512, 1)
hgemm(const __half* __restrict__ Ah, const __half* __restrict__ Al,
      const __half* __restrict__ Bh, const __half* __restrict__ Bl,
      void* __restrict__ Cv, __half* __restrict__ Cl,
      int K, int lda, int ldb, int ldc,
      long long sA, long long sB, long long sC)
{
    constexpr int WM = MT / 32;           // warps along M
    constexpr int WN = NT / 64;           // warps along N
    static_assert(WM * WN == 16, "16 warps");
    constexpr int OAL   = MT * 80;
    constexpr int OB    = (ASPL ? 2 : 1) * MT * 80;
    constexpr int OBL   = OB + NT * 80;
    constexpr int STAGE = ((ASPL ? 2 : 1) * MT + (BSPL ? 2 : 1) * NT) * 80;

    const int m0 = blockIdx.y * MT;
    const int n0 = blockIdx.x * NT;
    if (CSKIP && n0 > m0) return;

    extern __shared__ __align__(1024) char smem[];
    const uint32_t sb = s2u(smem);

    const int tid = threadIdx.x;
    const int w = tid >> 5, l = tid & 31;
    const int wm = w % WM, wn = w / WM;

    const __half* Ahz = Ah + (long long)blockIdx.z * sA;
    const __half* Alz = ASPL ? Al + (long long)blockIdx.z * sA : nullptr;
    const __half* Bhz = Bh + (long long)blockIdx.z * sB;
    const __half* Blz = BSPL ? Bl + (long long)blockIdx.z * sB : nullptr;

    const int kend = KLIM ? min(K, m0 + MT) : K;
    const int nst = kend >> 5;

    auto load_tile = [&](const __half* G, int ld, uint32_t dst, int T) {
        // T*4 16B-chunks, stride-512 over threads (T in {128,256} -> 1 or 2 iters)
        for (int c = tid; c < T * 4; c += 512) {
            const int row = c >> 2, cb = (c & 3) << 4;
            CPA16(dst + row * 80 + cb, (const char*)(G + (long long)row * ld) + cb);
        }
    };

    auto load_stage = [&](int s, int buf) {
        const int k0 = s << 5;
        const uint32_t st = sb + buf * STAGE;
        load_tile(Ahz + (long long)m0 * lda + k0, lda, st, MT);
        if (ASPL) load_tile(Alz + (long long)m0 * lda + k0, lda, st + OAL, MT);
        load_tile(Bhz + (long long)n0 * ldb + k0, ldb, st + OB, NT);
        if (BSPL) load_tile(Blz + (long long)n0 * ldb + k0, ldb, st + OBL, NT);
    };

    float acc[2][8][4];
    #pragma unroll
    for (int i = 0; i < 2; i++)
        #pragma unroll
        for (int j = 0; j < 8; j++)
            #pragma unroll
            for (int c = 0; c < 4; c++) acc[i][j][c] = 0.f;

    // prologue: stages 0..2 in flight
    #pragma unroll
    for (int i = 0; i < 3; i++) {
        if (i < nst) load_stage(i, i);
        CPCOMMIT();
    }

    // ldmatrix lane coords
    const int arow = (l & 7) + ((l >> 3) & 1) * 8;
    const int akb0 = ((l >> 4) & 1) * 16;
    const int brow = (l & 7) + ((l >> 4) & 1) * 8;
    const int bkb0 = ((l >> 3) & 1) * 16;

    for (int s = 0; s < nst; s++) {
        CPWAIT2();                 // stage s copy complete (<=2 groups pending)
        __syncthreads();           // buffer (s+3)&3 free of iter s-1 readers
        if (s + 3 < nst) load_stage(s + 3, (s + 3) & 3);
        CPCOMMIT();                // real or empty: uniform group count

        const uint32_t st = sb + (s & 3) * STAGE;
        #pragma unroll
        for (int kt = 0; kt < 2; kt++) {
            uint32_t b[8][2];
            #pragma unroll
            for (int np = 0; np < 4; np++) {
                const int row = wn * 64 + np * 16 + brow;
                LDMX4(b[np*2][0], b[np*2][1], b[np*2+1][0], b[np*2+1][1],
                      st + OB + row * 80 + kt * 32 + bkb0);
            }
            uint32_t a[2][4];
            #pragma unroll
            for (int mt = 0; mt < 2; mt++) {
                const int row = wm * 32 + mt * 16 + arow;
                LDMX4(a[mt][0], a[mt][1], a[mt][2], a[mt][3],
                      st + row * 80 + kt * 32 + akb0);
            }
            #pragma unroll
            for (int mt = 0; mt < 2; mt++)
                #pragma unroll
                for (int nt = 0; nt < 8; nt++)
                    MMA16816(acc[mt][nt], a[mt], b[nt]);

            if (ASPL) {
                uint32_t a2[2][4];
                #pragma unroll
                for (int mt = 0; mt < 2; mt++) {
                    const int row = wm * 32 + mt * 16 + arow;
                    LDMX4(a2[mt][0], a2[mt][1], a2[mt][2], a2[mt][3],
                          st + OAL + row * 80 + kt * 32 + akb0);
                }
                #pragma unroll
                for (int mt = 0; mt < 2; mt++)
                    #pragma unroll
                    for (int nt = 0; nt < 8; nt++)
                        MMA16816(acc[mt][nt], a2[mt], b[nt]);
            }
            if (BSPL) {
                uint32_t b2[8][2];
                #pragma unroll
                for (int np = 0; np < 4; np++) {
                    const int row = wn * 64 + np * 16 + brow;
                    LDMX4(b2[np*2][0], b2[np*2][1], b2[np*2+1][0], b2[np*2+1][1],
                          st + OBL + row * 80 + kt * 32 + bkb0);
                }
                #pragma unroll
                for (int mt = 0; mt < 2; mt++)
                    #pragma unroll
                    for (int nt = 0; nt < 8; nt++)
                        MMA16816(acc[mt][nt], a[mt], b2[nt]);
            }
        }
    }

    // ----- epilogue -----
    #pragma unroll
    for (int mt = 0; mt < 2; mt++) {
        #pragma unroll
        for (int nt = 0; nt < 8; nt++) {
            const int row = m0 + wm * 32 + mt * 16 + (l >> 2);
            const int col = n0 + wn * 64 + nt * 8 + (l & 3) * 2;
            const float c0 = acc[mt][nt][0], c1 = acc[mt][nt][1];
            const float c2 = acc[mt][nt][2], c3 = acc[mt][nt][3];
            if (CHALF) {
                __half* Ch  = (__half*)Cv + (long long)blockIdx.z * sC;
                __half* Cll = Cl + (long long)blockIdx.z * sC;
                __half h0 = __float2half_rn(c0), h1 = __float2half_rn(c1);
                *(__half2*)(Ch  + (long long)row * ldc + col) = __halves2half2(h0, h1);
                *(__half2*)(Cll + (long long)row * ldc + col) =
                    __halves2half2(__float2half_rn(c0 - __half2float(h0)),
                                   __float2half_rn(c1 - __half2float(h1)));
                __half h2 = __float2half_rn(c2), h3 = __float2half_rn(c3);
                *(__half2*)(Ch  + (long long)(row + 8) * ldc + col) = __halves2half2(h2, h3);
                *(__half2*)(Cll + (long long)(row + 8) * ldc + col) =
                    __halves2half2(__float2half_rn(c2 - __half2float(h2)),
                                   __float2half_rn(c3 - __half2float(h3)));
            } else {
                float* Cf = (float*)Cv + (long long)blockIdx.z * sC;
                *(float2*)(Cf + (long long)row * ldc + col)       = make_float2(c0, c1);
                *(float2*)(Cf + (long long)(row + 8) * ldc + col) = make_float2(c2, c3);
            }
        }
    }
}

// ---------------------------------------------------------------------------
// fp32 -> split-fp16, float4 vectorized (n divisible by 1024)
// ---------------------------------------------------------------------------
__global__ void f2hsplit(const float* __restrict__ in, __half* __restrict__ oh,
                         __half* __restrict__ ol, int n)
{
    int i = (blockIdx.x * 256 + threadIdx.x) * 4;
    if (i >= n) return;
    float4 v = *(const float4*)(in + i);
    __half hx = __float2half_rn(v.x), hy = __float2half_rn(v.y);
    __half hz = __float2half_rn(v.z), hw = __float2half_rn(v.w);
    *(__half2*)(oh + i)     = __halves2half2(hx, hy);
    *(__half2*)(oh + i + 2) = __halves2half2(hz, hw);
    *(__half2*)(ol + i) = __halves2half2(
        __float2half_rn(v.x - __half2float(hx)), __float2half_rn(v.y - __half2float(hy)));
    *(__half2*)(ol + i + 2) = __halves2half2(
        __float2half_rn(v.z - __half2float(hz)), __float2half_rn(v.w - __half2float(hw)));
}

// fp32 -> fp16 (hi only), float4 vectorized
__global__ void f2h(const float* __restrict__ in, __half* __restrict__ oh, int n)
{
    int i = (blockIdx.x * 256 + threadIdx.x) * 4;
    if (i >= n) return;
    float4 v = *(const float4*)(in + i);
    *(__half2*)(oh + i)     = __halves2half2(__float2half_rn(v.x), __float2half_rn(v.y));
    *(__half2*)(oh + i + 2) = __halves2half2(__float2half_rn(v.z), __float2half_rn(v.w));
}

// ---------------------------------------------------------------------------
__global__ void rope_kernel(__half* Qh, __half* Ql, __half* Kh, __half* Kl,
                            const float* __restrict__ cosT, const float* __restrict__ sinT)
{
    int idx = blockIdx.x * blockDim.x + threadIdx.x;
    if (idx >= SEQ * NH * (ROPE / 2)) return;
    int i = idx & 31, h = (idx >> 5) & 15, s = idx >> 9;
    float c = cosT[s * 32 + i], sn = sinT[s * 32 + i];
    long long base = (long long)s * QKLD + h * HD + NOPE + 2 * i;
    float a, b, ra, rb; __half hh;
    a = __half2float(Qh[base])   + __half2float(Ql[base]);
    b = __half2float(Qh[base+1]) + __half2float(Ql[base+1]);
    ra = a * c - b * sn; rb = a * sn + b * c;
    hh = __float2half_rn(ra); Qh[base]   = hh; Ql[base]   = __float2half_rn(ra - __half2float(hh));
    hh = __float2half_rn(rb); Qh[base+1] = hh; Ql[base+1] = __float2half_rn(rb - __half2float(hh));
    a = __half2float(Kh[base])   + __half2float(Kl[base]);
    b = __half2float(Kh[base+1]) + __half2float(Kl[base+1]);
    ra = a * c - b * sn; rb = a * sn + b * c;
    hh = __float2half_rn(ra); Kh[base]   = hh; Kl[base]   = __float2half_rn(ra - __half2float(hh));
    hh = __float2half_rn(rb); Kh[base+1] = hh; Kl[base+1] = __float2half_rn(rb - __half2float(hh));
}

// ---------------------------------------------------------------------------
__global__ void transpose_h(const __half* __restrict__ in, __half* __restrict__ out)
{
    __shared__ __half t[32][33];
    int x = blockIdx.x * 32 + threadIdx.x;
    int y = blockIdx.y * 32 + threadIdx.y;
    #pragma unroll
    for (int j = 0; j < 32; j += 8)
        t[threadIdx.y + j][threadIdx.x] = in[(long long)(y + j) * DIM + x];
    __syncthreads();
    x = blockIdx.y * 32 + threadIdx.x;
    y = blockIdx.x * 32 + threadIdx.y;
    #pragma unroll
    for (int j = 0; j < 32; j += 8)
        out[(long long)(y + j) * SEQ + x] = t[threadIdx.x][threadIdx.y + j];
}

// ---------------------------------------------------------------------------
__global__ void softmax_causal(const float* __restrict__ S, __half* __restrict__ P, float scale)
{
    const int s = blockIdx.x, h = blockIdx.y;
    const float* row = S + ((long long)h * SEQ + s) * SEQ;
    __half* prow = P + ((long long)h * SEQ + s) * SEQ;
    const int n = s + 1;
    const int tid = threadIdx.x;
    __shared__ float buf[SEQ];
    __shared__ float red[8];

    float m = -1e30f;
    for (int t = tid; t < n; t += 256) { float v = row[t]; buf[t] = v; m = fmaxf(m, v); }
    #pragma unroll
    for (int o = 16; o; o >>= 1) m = fmaxf(m, __shfl_xor_sync(0xffffffffu, m, o));
    if ((tid & 31) == 0) red[tid >> 5] = m;
    __syncthreads();
    if (tid < 8) {
        float v = red[tid];
        #pragma unroll
        for (int o = 4; o; o >>= 1) v = fmaxf(v, __shfl_xor_sync(0xffu, v, o));
        if (tid == 0) red[0] = v;
    }
    __syncthreads();
    m = red[0];
    __syncthreads();

    float sum = 0.f;
    for (int t = tid; t < n; t += 256) {
        float e = __expf((buf[t] - m) * scale);
        buf[t] = e; sum += e;
    }
    #pragma unroll
    for (int o = 16; o; o >>= 1) sum += __shfl_xor_sync(0xffffffffu, sum, o);
    if ((tid & 31) == 0) red[tid >> 5] = sum;
    __syncthreads();
    if (tid < 8) {
        float v = red[tid];
        #pragma unroll
        for (int o = 4; o; o >>= 1) v += __shfl_xor_sync(0xffu, v, o);
        if (tid == 0) red[0] = v;
    }
    __syncthreads();
    const float inv = 1.f / red[0];
    __syncthreads();

    for (int t = tid * 2; t < SEQ; t += 512) {
        float a = (t     < n) ? buf[t]     * inv : 0.f;
        float b = (t + 1 < n) ? buf[t + 1] * inv : 0.f;
        *(__half2*)(prow + t) = __halves2half2(__float2half_rn(a), __float2half_rn(b));
    }
}

// ---------------------------------------------------------------------------
extern "C" void kernel_launch(void* const* d_in, const int* in_sizes, int n_in,
                              void* d_out, int out_size)
{
    const float* x  = (const float*)d_in[0];
    const float* wq = (const float*)d_in[1];
    const float* wk = (const float*)d_in[2];
    const float* wv = (const float*)d_in[3];
    const float* wo = (const float*)d_in[4];
    const float* fc = (const float*)d_in[5];
    const float* fs = (const float*)d_in[6];
    float* out = (float*)d_out;

    __half *xh, *xl, *wqh, *wkh, *wvh, *woh;
    __half *qh, *ql, *kh, *kl, *vh, *vl, *vth, *vtl, *p, *oh, *ol;
    float* sc;
    cudaGetSymbolAddress((void**)&xh, g_xh);   cudaGetSymbolAddress((void**)&xl, g_xl);
    cudaGetSymbolAddress((void**)&wqh, g_wqh);
    cudaGetSymbolAddress((void**)&wkh, g_wkh);
    cudaGetSymbolAddress((void**)&wvh, g_wvh);
    cudaGetSymbolAddress((void**)&woh, g_woh);
    cudaGetSymbolAddress((void**)&qh, g_qh);   cudaGetSymbolAddress((void**)&ql, g_ql);
    cudaGetSymbolAddress((void**)&kh, g_kh);   cudaGetSymbolAddress((void**)&kl, g_kl);
    cudaGetSymbolAddress((void**)&vh, g_vh);   cudaGetSymbolAddress((void**)&vl, g_vl);
    cudaGetSymbolAddress((void**)&vth, g_vth); cudaGetSymbolAddress((void**)&vtl, g_vtl);
    cudaGetSymbolAddress((void**)&p, g_p);
    cudaGetSymbolAddress((void**)&oh, g_oh);   cudaGetSymbolAddress((void**)&ol, g_ol);
    cudaGetSymbolAddress((void**)&sc, g_s);

    const int SMEM4 = 4 * 40960;  // 163840: 4 stages x 512 rows x 80B
    cudaFuncSetAttribute((const void*)hgemm<128,256,1,0,0,0,1>, cudaFuncAttributeMaxDynamicSharedMemorySize, SMEM4);
    cudaFuncSetAttribute((const void*)hgemm<128,256,1,0,1,0,0>, cudaFuncAttributeMaxDynamicSharedMemorySize, SMEM4);
    cudaFuncSetAttribute((const void*)hgemm<256,128,0,1,0,1,1>, cudaFuncAttributeMaxDynamicSharedMemorySize, SMEM4);
    cudaFuncSetAttribute((const void*)hgemm<128,256,1,0,0,0,0>, cudaFuncAttributeMaxDynamicSharedMemorySize, SMEM4);

    // conversions: activations split, weights hi-only
    f2hsplit<<<SEQ * DIM / 1024, 256>>>(x, xh, xl, SEQ * DIM);
    f2h<<<QKLD * DIM / 1024, 256>>>(wq, wqh, QKLD * DIM);
    f2h<<<QKLD * DIM / 1024, 256>>>(wk, wkh, QKLD * DIM);
    f2h<<<DIM * DIM / 1024, 256>>>(wv, wvh, DIM * DIM);
    f2h<<<DIM * DIM / 1024, 256>>>(wo, woh, DIM * DIM);

    // projections: A = x (split), B = W (single fp16), split-fp16 out
    hgemm<128,256,1,0,0,0,1><<<dim3(QKLD / 256, SEQ / 128), 512, SMEM4>>>(
        xh, xl, wqh, nullptr, qh, ql, DIM, DIM, DIM, QKLD, 0, 0, 0);
    hgemm<128,256,1,0,0,0,1><<<dim3(QKLD / 256, SEQ / 128), 512, SMEM4>>>(
        xh, xl, wkh, nullptr, kh, kl, DIM, DIM, DIM, QKLD, 0, 0, 0);
    hgemm<128,256,1,0,0,0,1><<<dim3(DIM / 256, SEQ / 128), 512, SMEM4>>>(
        xh, xl, wvh, nullptr, vh, vl, DIM, DIM, DIM, DIM, 0, 0, 0);

    // RoPE
    rope_kernel<<<(SEQ * NH * 32 + 255) / 256, 256>>>(qh, ql, kh, kl, fc, fs);

    // V transpose -> [DIM][SEQ] K-major for PV
    transpose_h<<<dim3(64, 64), dim3(32, 8)>>>(vh, vth);
    transpose_h<<<dim3(64, 64), dim3(32, 8)>>>(vl, vtl);

    // scores (causal block skip): A = q (split), B = k hi, fp32 out
    // kept blocks may contain above-diagonal garbage; softmax never reads it
    hgemm<128,256,1,0,1,0,0><<<dim3(SEQ / 256, SEQ / 128, NH), 512, SMEM4>>>(
        qh, ql, kh, nullptr, sc, nullptr, HD, QKLD, QKLD, SEQ,
        HD, HD, (long long)SEQ * SEQ);

    // softmax -> fp16 probs (zero-padded beyond diagonal)
    softmax_causal<<<dim3(SEQ, NH), 256>>>(sc, p, rsqrtf((float)HD));

    // PV (causal K-limit): A = probs (single), B = V (split), M-wide tile
    hgemm<256,128,0,1,0,1,1><<<dim3(1, SEQ / 256, NH), 512, SMEM4>>>(
        p, nullptr, vth, vtl, oh, ol, SEQ, SEQ, SEQ, DIM,
        (long long)SEQ * SEQ, (long long)VD * SEQ, VD);

    // output projection: A = o (split), B = wo hi, fp32 out
    hgemm<128,256,1,0,0,0,0><<<dim3(DIM / 256, SEQ / 128), 512, SMEM4>>>(
        oh, ol, woh, nullptr, out, nullptr, DIM, DIM, DIM, DIM, 0, 0, 0);
}

// round 7
// speedup vs baseline: 1.2228x; 1.2228x over previous
#include <cuda_runtime.h>
#include <cuda_fp16.h>
#include <cstdint>
#include <math.h>

#define SEQ 2048
#define DIM 2048
#define NH 16
#define HD 192
#define NOPE 128
#define ROPE 64
#define VD 128
#define QKLD (NH*HD)   // 3072

// ---------------------------------------------------------------------------
// scratch (allocation-free __device__ globals)
// ---------------------------------------------------------------------------
__device__ __half g_xh [SEQ*DIM],   g_xl [SEQ*DIM];
__device__ __half g_wqh[QKLD*DIM];
__device__ __half g_wkh[QKLD*DIM];
__device__ __half g_wvh[DIM*DIM];
__device__ __half g_woh[DIM*DIM];
__device__ __half g_qh [SEQ*QKLD],  g_ql [SEQ*QKLD];
__device__ __half g_kh [SEQ*QKLD],  g_kl [SEQ*QKLD];
__device__ __half g_vh [SEQ*DIM],   g_vl [SEQ*DIM];
__device__ __half g_vth[DIM*SEQ],   g_vtl[DIM*SEQ];
__device__ float  g_s[(long long)NH*SEQ*SEQ];
__device__ __half g_p[(long long)NH*SEQ*SEQ];
__device__ __half g_oh [SEQ*DIM],   g_ol [SEQ*DIM];

// ---------------------------------------------------------------------------
static __device__ __forceinline__ uint32_t s2u(const void* p) {
    uint32_t a;
    asm("{ .reg .u64 t; cvta.to.shared.u64 t, %1; cvt.u32.u64 %0, t; }" : "=r"(a) : "l"(p));
    return a;
}
#define CPA16(dst, src) \
    asm volatile("cp.async.cg.shared.global [%0], [%1], 16;" :: "r"(dst), "l"(src))
#define CPCOMMIT() asm volatile("cp.async.commit_group;" ::: "memory")
#define CPWAIT1()  asm volatile("cp.async.wait_group 1;" ::: "memory")

#define LDMX4(r0, r1, r2, r3, a) \
    asm volatile("ldmatrix.sync.aligned.m8n8.x4.shared.b16 {%0,%1,%2,%3}, [%4];" \
                 : "=r"(r0), "=r"(r1), "=r"(r2), "=r"(r3) : "r"(a))

#define MMA16816(d, a, b) \
    asm volatile("mma.sync.aligned.m16n8k16.row.col.f32.f16.f16.f32 " \
                 "{%0,%1,%2,%3},{%4,%5,%6,%7},{%8,%9},{%0,%1,%2,%3};" \
                 : "+f"((d)[0]), "+f"((d)[1]), "+f"((d)[2]), "+f"((d)[3]) \
                 : "r"((a)[0]), "r"((a)[1]), "r"((a)[2]), "r"((a)[3]), \
                   "r"((b)[0]), "r"((b)[1]))

// ---------------------------------------------------------------------------
// HMMA GEMM core:  C[tile] = A * B^T  (K-major), 2-term split numerics.
//   acc = Ah*Bh^T  [+ Al*Bh^T if ASPL]  [+ Ah*Bl^T if BSPL]
//   Tile 128x128, 256 threads, warp tile 32x64, 3-stage cp.async pipeline.
//   CHALF: write split-fp16 (Ch,Cl) else fp32.
// Smem/stage: (2+ASPL+BSPL) tiles x 128 rows x 80B = 30720 B; x3 stages.
// ---------------------------------------------------------------------------
template<bool ASPL, bool BSPL, bool CHALF>
static __device__ __forceinline__ void
hgemm_core(const __half* __restrict__ Ahz, const __half* __restrict__ Alz,
           const __half* __restrict__ Bhz, const __half* __restrict__ Blz,
           void* __restrict__ Cv, __half* __restrict__ Cl,
           int m0, int n0, int kend, int lda, int ldb, int ldc)
{
    constexpr int STAGE = (2 + (ASPL ? 1 : 0) + (BSPL ? 1 : 0)) * 10240;
    constexpr int OAL = 10240;
    constexpr int OB  = (ASPL ? 2 : 1) * 10240;
    constexpr int OBL = OB + 10240;

    extern __shared__ __align__(1024) char smem[];
    const uint32_t sb = s2u(smem);

    const int tid = threadIdx.x;
    const int w = tid >> 5, l = tid & 31;
    const int wm = w & 3, wn = w >> 2;

    const int nst = kend >> 5;

    const int lrow = tid >> 2;             // rows lrow, lrow+64
    const int lcb  = (tid & 3) << 4;       // 16B chunk in row

    auto load_tile = [&](const __half* G, int ld, uint32_t dstbase) {
        #pragma unroll
        for (int i = 0; i < 2; i++) {
            const int row = lrow + i * 64;
            CPA16(dstbase + row * 80 + lcb,
                  (const char*)(G + (long long)row * ld) + lcb);
        }
    };

    auto load_stage = [&](int s, int buf) {
        const int k0 = s << 5;
        const uint32_t st = sb + buf * STAGE;
        load_tile(Ahz + (long long)m0 * lda + k0, lda, st);
        if (ASPL) load_tile(Alz + (long long)m0 * lda + k0, lda, st + OAL);
        load_tile(Bhz + (long long)n0 * ldb + k0, ldb, st + OB);
        if (BSPL) load_tile(Blz + (long long)n0 * ldb + k0, ldb, st + OBL);
    };

    float acc[2][8][4];
    #pragma unroll
    for (int i = 0; i < 2; i++)
        #pragma unroll
        for (int j = 0; j < 8; j++)
            #pragma unroll
            for (int c = 0; c < 4; c++) acc[i][j][c] = 0.f;

    // prologue: stages 0,1 in flight
    #pragma unroll
    for (int i = 0; i < 2; i++) {
        if (i < nst) load_stage(i, i);
        CPCOMMIT();
    }

    const int arow = (l & 7) + ((l >> 3) & 1) * 8;
    const int akb0 = ((l >> 4) & 1) * 16;
    const int brow = (l & 7) + ((l >> 4) & 1) * 8;
    const int bkb0 = ((l >> 3) & 1) * 16;

    for (int s = 0; s < nst; s++) {
        CPWAIT1();                 // stage s complete (<=1 group pending)
        __syncthreads();           // all warps done reading buffer (s-1)%3
        if (s + 2 < nst) load_stage(s + 2, (s + 2) % 3);
        CPCOMMIT();                // real or empty: uniform group count

        const uint32_t st = sb + (s % 3) * STAGE;
        #pragma unroll
        for (int kt = 0; kt < 2; kt++) {
            uint32_t b[8][2];
            #pragma unroll
            for (int np = 0; np < 4; np++) {
                const int row = wn * 64 + np * 16 + brow;
                LDMX4(b[np*2][0], b[np*2][1], b[np*2+1][0], b[np*2+1][1],
                      st + OB + row * 80 + kt * 32 + bkb0);
            }
            uint32_t a[2][4];
            #pragma unroll
            for (int mt = 0; mt < 2; mt++) {
                const int row = wm * 32 + mt * 16 + arow;
                LDMX4(a[mt][0], a[mt][1], a[mt][2], a[mt][3],
                      st + row * 80 + kt * 32 + akb0);
            }
            #pragma unroll
            for (int mt = 0; mt < 2; mt++)
                #pragma unroll
                for (int nt = 0; nt < 8; nt++)
                    MMA16816(acc[mt][nt], a[mt], b[nt]);

            if (ASPL) {
                uint32_t a2[2][4];
                #pragma unroll
                for (int mt = 0; mt < 2; mt++) {
                    const int row = wm * 32 + mt * 16 + arow;
                    LDMX4(a2[mt][0], a2[mt][1], a2[mt][2], a2[mt][3],
                          st + OAL + row * 80 + kt * 32 + akb0);
                }
                #pragma unroll
                for (int mt = 0; mt < 2; mt++)
                    #pragma unroll
                    for (int nt = 0; nt < 8; nt++)
                        MMA16816(acc[mt][nt], a2[mt], b[nt]);
            }
            if (BSPL) {
                uint32_t b2[8][2];
                #pragma unroll
                for (int np = 0; np < 4; np++) {
                    const int row = wn * 64 + np * 16 + brow;
                    LDMX4(b2[np*2][0], b2[np*2][1], b2[np*2+1][0], b2[np*2+1][1],
                          st + OBL + row * 80 + kt * 32 + bkb0);
                }
                #pragma unroll
                for (int mt = 0; mt < 2; mt++)
                    #pragma unroll
                    for (int nt = 0; nt < 8; nt++)
                        MMA16816(acc[mt][nt], a[mt], b2[nt]);
            }
        }
    }

    // ----- epilogue -----
    #pragma unroll
    for (int mt = 0; mt < 2; mt++) {
        #pragma unroll
        for (int nt = 0; nt < 8; nt++) {
            const int row = m0 + wm * 32 + mt * 16 + (l >> 2);
            const int col = n0 + wn * 64 + nt * 8 + (l & 3) * 2;
            const float c0 = acc[mt][nt][0], c1 = acc[mt][nt][1];
            const float c2 = acc[mt][nt][2], c3 = acc[mt][nt][3];
            if (CHALF) {
                __half* Ch  = (__half*)Cv;
                __half h0 = __float2half_rn(c0), h1 = __float2half_rn(c1);
                *(__half2*)(Ch + (long long)row * ldc + col) = __halves2half2(h0, h1);
                *(__half2*)(Cl + (long long)row * ldc + col) =
                    __halves2half2(__float2half_rn(c0 - __half2float(h0)),
                                   __float2half_rn(c1 - __half2float(h1)));
                __half h2 = __float2half_rn(c2), h3 = __float2half_rn(c3);
                *(__half2*)(Ch + (long long)(row + 8) * ldc + col) = __halves2half2(h2, h3);
                *(__half2*)(Cl + (long long)(row + 8) * ldc + col) =
                    __halves2half2(__float2half_rn(c2 - __half2float(h2)),
                                   __float2half_rn(c3 - __half2float(h3)));
            } else {
                float* Cf = (float*)Cv;
                *(float2*)(Cf + (long long)row * ldc + col)       = make_float2(c0, c1);
                *(float2*)(Cf + (long long)(row + 8) * ldc + col) = make_float2(c2, c3);
            }
        }
    }
}

// ---------------------------------------------------------------------------
// generic batched GEMM wrapper (scores / PV / WO)
// ---------------------------------------------------------------------------
template<bool ASPL, bool BSPL, bool CSKIP, bool KLIM, bool CHALF>
__global__ void __launch_bounds__(256, 2)
hgemm(const __half* __restrict__ Ah, const __half* __restrict__ Al,
      const __half* __restrict__ Bh, const __half* __restrict__ Bl,
      void* __restrict__ Cv, __half* __restrict__ Cl,
      int K, int lda, int ldb, int ldc,
      long long sA, long long sB, long long sC)
{
    const int m0 = blockIdx.y * 128;
    const int n0 = blockIdx.x * 128;
    if (CSKIP && n0 > m0) return;
    const int kend = KLIM ? min(K, m0 + 128) : K;

    const __half* Ahz = Ah + (long long)blockIdx.z * sA;
    const __half* Alz = ASPL ? Al + (long long)blockIdx.z * sA : nullptr;
    const __half* Bhz = Bh + (long long)blockIdx.z * sB;
    const __half* Blz = BSPL ? Bl + (long long)blockIdx.z * sB : nullptr;
    void*   Cvz = (char*)Cv + (long long)blockIdx.z * sC * (CHALF ? 2 : 4);
    __half* Clz = CHALF ? Cl + (long long)blockIdx.z * sC : nullptr;

    hgemm_core<ASPL, BSPL, CHALF>(Ahz, Alz, Bhz, Blz, Cvz, Clz,
                                  m0, n0, kend, lda, ldb, ldc);
}

// ---------------------------------------------------------------------------
// fused QKV projection: z=0 -> Q (24 n-blocks), z=1 -> K (24), z=2 -> V (16)
// ---------------------------------------------------------------------------
__global__ void __launch_bounds__(256, 2)
hgemm_qkv(const __half* __restrict__ xh, const __half* __restrict__ xl,
          const __half* __restrict__ wqh, const __half* __restrict__ wkh,
          const __half* __restrict__ wvh,
          __half* __restrict__ qh, __half* __restrict__ ql,
          __half* __restrict__ kh, __half* __restrict__ kl,
          __half* __restrict__ vh, __half* __restrict__ vl)
{
    const int z = blockIdx.z;
    const __half* B; __half *Ch, *Cll; int nb, ldc;
    if (z == 0)      { B = wqh; Ch = qh; Cll = ql; nb = 24; ldc = QKLD; }
    else if (z == 1) { B = wkh; Ch = kh; Cll = kl; nb = 24; ldc = QKLD; }
    else             { B = wvh; Ch = vh; Cll = vl; nb = 16; ldc = DIM;  }
    if ((int)blockIdx.x >= nb) return;

    hgemm_core<true, false, true>(xh, xl, B, nullptr, Ch, Cll,
                                  blockIdx.y * 128, blockIdx.x * 128,
                                  DIM, DIM, DIM, ldc);
}

// ---------------------------------------------------------------------------
// fp32 -> split-fp16, float4 vectorized (n divisible by 1024)
// ---------------------------------------------------------------------------
__global__ void f2hsplit(const float* __restrict__ in, __half* __restrict__ oh,
                         __half* __restrict__ ol, int n)
{
    int i = (blockIdx.x * 256 + threadIdx.x) * 4;
    if (i >= n) return;
    float4 v = *(const float4*)(in + i);
    __half hx = __float2half_rn(v.x), hy = __float2half_rn(v.y);
    __half hz = __float2half_rn(v.z), hw = __float2half_rn(v.w);
    *(__half2*)(oh + i)     = __halves2half2(hx, hy);
    *(__half2*)(oh + i + 2) = __halves2half2(hz, hw);
    *(__half2*)(ol + i) = __halves2half2(
        __float2half_rn(v.x - __half2float(hx)), __float2half_rn(v.y - __half2float(hy)));
    *(__half2*)(ol + i + 2) = __halves2half2(
        __float2half_rn(v.z - __half2float(hz)), __float2half_rn(v.w - __half2float(hw)));
}

// fused fp32 -> fp16 (hi only) for the 4 weight matrices; z selects array
__global__ void f2h4(const float* __restrict__ wq, const float* __restrict__ wk,
                     const float* __restrict__ wv, const float* __restrict__ wo,
                     __half* __restrict__ oq, __half* __restrict__ ok,
                     __half* __restrict__ ov, __half* __restrict__ oo)
{
    const int z = blockIdx.z;
    const float* in; __half* oh; int n;
    if (z == 0)      { in = wq; oh = oq; n = QKLD * DIM; }
    else if (z == 1) { in = wk; oh = ok; n = QKLD * DIM; }
    else if (z == 2) { in = wv; oh = ov; n = DIM * DIM; }
    else             { in = wo; oh = oo; n = DIM * DIM; }
    int i = (blockIdx.x * 256 + threadIdx.x) * 4;
    if (i >= n) return;
    float4 v = *(const float4*)(in + i);
    *(__half2*)(oh + i)     = __halves2half2(__float2half_rn(v.x), __float2half_rn(v.y));
    *(__half2*)(oh + i + 2) = __halves2half2(__float2half_rn(v.z), __float2half_rn(v.w));
}

// ---------------------------------------------------------------------------
__global__ void rope_kernel(__half* Qh, __half* Ql, __half* Kh, __half* Kl,
                            const float* __restrict__ cosT, const float* __restrict__ sinT)
{
    int idx = blockIdx.x * blockDim.x + threadIdx.x;
    if (idx >= SEQ * NH * (ROPE / 2)) return;
    int i = idx & 31, h = (idx >> 5) & 15, s = idx >> 9;
    float c = cosT[s * 32 + i], sn = sinT[s * 32 + i];
    long long base = (long long)s * QKLD + h * HD + NOPE + 2 * i;
    float a, b, ra, rb; __half hh;
    a = __half2float(Qh[base])   + __half2float(Ql[base]);
    b = __half2float(Qh[base+1]) + __half2float(Ql[base+1]);
    ra = a * c - b * sn; rb = a * sn + b * c;
    hh = __float2half_rn(ra); Qh[base]   = hh; Ql[base]   = __float2half_rn(ra - __half2float(hh));
    hh = __float2half_rn(rb); Qh[base+1] = hh; Ql[base+1] = __float2half_rn(rb - __half2float(hh));
    a = __half2float(Kh[base])   + __half2float(Kl[base]);
    b = __half2float(Kh[base+1]) + __half2float(Kl[base+1]);
    ra = a * c - b * sn; rb = a * sn + b * c;
    hh = __float2half_rn(ra); Kh[base]   = hh; Kl[base]   = __float2half_rn(ra - __half2float(hh));
    hh = __float2half_rn(rb); Kh[base+1] = hh; Kl[base+1] = __float2half_rn(rb - __half2float(hh));
}

// ---------------------------------------------------------------------------
// fused V transpose: z=0 -> (vh->vth), z=1 -> (vl->vtl)
// ---------------------------------------------------------------------------
__global__ void transpose_h2(const __half* __restrict__ in0, __half* __restrict__ out0,
                             const __half* __restrict__ in1, __half* __restrict__ out1)
{
    const __half* in  = blockIdx.z ? in1  : in0;
    __half*       out = blockIdx.z ? out1 : out0;
    __shared__ __half t[32][33];
    int x = blockIdx.x * 32 + threadIdx.x;
    int y = blockIdx.y * 32 + threadIdx.y;
    #pragma unroll
    for (int j = 0; j < 32; j += 8)
        t[threadIdx.y + j][threadIdx.x] = in[(long long)(y + j) * DIM + x];
    __syncthreads();
    x = blockIdx.y * 32 + threadIdx.x;
    y = blockIdx.x * 32 + threadIdx.y;
    #pragma unroll
    for (int j = 0; j < 32; j += 8)
        out[(long long)(y + j) * SEQ + x] = t[threadIdx.x][threadIdx.y + j];
}

// ---------------------------------------------------------------------------
__global__ void softmax_causal(const float* __restrict__ S, __half* __restrict__ P, float scale)
{
    const int s = blockIdx.x, h = blockIdx.y;
    const float* row = S + ((long long)h * SEQ + s) * SEQ;
    __half* prow = P + ((long long)h * SEQ + s) * SEQ;
    const int n = s + 1;
    const int tid = threadIdx.x;
    __shared__ float buf[SEQ];
    __shared__ float red[8];

    float m = -1e30f;
    for (int t = tid; t < n; t += 256) { float v = row[t]; buf[t] = v; m = fmaxf(m, v); }
    #pragma unroll
    for (int o = 16; o; o >>= 1) m = fmaxf(m, __shfl_xor_sync(0xffffffffu, m, o));
    if ((tid & 31) == 0) red[tid >> 5] = m;
    __syncthreads();
    if (tid < 8) {
        float v = red[tid];
        #pragma unroll
        for (int o = 4; o; o >>= 1) v = fmaxf(v, __shfl_xor_sync(0xffu, v, o));
        if (tid == 0) red[0] = v;
    }
    __syncthreads();
    m = red[0];
    __syncthreads();

    float sum = 0.f;
    for (int t = tid; t < n; t += 256) {
        float e = __expf((buf[t] - m) * scale);
        buf[t] = e; sum += e;
    }
    #pragma unroll
    for (int o = 16; o; o >>= 1) sum += __shfl_xor_sync(0xffffffffu, sum, o);
    if ((tid & 31) == 0) red[tid >> 5] = sum;
    __syncthreads();
    if (tid < 8) {
        float v = red[tid];
        #pragma unroll
        for (int o = 4; o; o >>= 1) v += __shfl_xor_sync(0xffu, v, o);
        if (tid == 0) red[0] = v;
    }
    __syncthreads();
    const float inv = 1.f / red[0];
    __syncthreads();

    for (int t = tid * 2; t < SEQ; t += 512) {
        float a = (t     < n) ? buf[t]     * inv : 0.f;
        float b = (t + 1 < n) ? buf[t + 1] * inv : 0.f;
        *(__half2*)(prow + t) = __halves2half2(__float2half_rn(a), __float2half_rn(b));
    }
}

// ---------------------------------------------------------------------------
extern "C" void kernel_launch(void* const* d_in, const int* in_sizes, int n_in,
                              void* d_out, int out_size)
{
    const float* x  = (const float*)d_in[0];
    const float* wq = (const float*)d_in[1];
    const float* wk = (const float*)d_in[2];
    const float* wv = (const float*)d_in[3];
    const float* wo = (const float*)d_in[4];
    const float* fc = (const float*)d_in[5];
    const float* fs = (const float*)d_in[6];
    float* out = (float*)d_out;

    __half *xh, *xl, *wqh, *wkh, *wvh, *woh;
    __half *qh, *ql, *kh, *kl, *vh, *vl, *vth, *vtl, *p, *oh, *ol;
    float* sc;
    cudaGetSymbolAddress((void**)&xh, g_xh);   cudaGetSymbolAddress((void**)&xl, g_xl);
    cudaGetSymbolAddress((void**)&wqh, g_wqh);
    cudaGetSymbolAddress((void**)&wkh, g_wkh);
    cudaGetSymbolAddress((void**)&wvh, g_wvh);
    cudaGetSymbolAddress((void**)&woh, g_woh);
    cudaGetSymbolAddress((void**)&qh, g_qh);   cudaGetSymbolAddress((void**)&ql, g_ql);
    cudaGetSymbolAddress((void**)&kh, g_kh);   cudaGetSymbolAddress((void**)&kl, g_kl);
    cudaGetSymbolAddress((void**)&vh, g_vh);   cudaGetSymbolAddress((void**)&vl, g_vl);
    cudaGetSymbolAddress((void**)&vth, g_vth); cudaGetSymbolAddress((void**)&vtl, g_vtl);
    cudaGetSymbolAddress((void**)&p, g_p);
    cudaGetSymbolAddress((void**)&oh, g_oh);   cudaGetSymbolAddress((void**)&ol, g_ol);
    cudaGetSymbolAddress((void**)&sc, g_s);

    const int SMEM3 = 3 * 30720;  // 92160 (3-tile stages)
    cudaFuncSetAttribute((const void*)hgemm_qkv,          cudaFuncAttributeMaxDynamicSharedMemorySize, SMEM3);
    cudaFuncSetAttribute((const void*)hgemm<1,0,1,0,0>,   cudaFuncAttributeMaxDynamicSharedMemorySize, SMEM3);
    cudaFuncSetAttribute((const void*)hgemm<0,1,0,1,1>,   cudaFuncAttributeMaxDynamicSharedMemorySize, SMEM3);
    cudaFuncSetAttribute((const void*)hgemm<1,0,0,0,0>,   cudaFuncAttributeMaxDynamicSharedMemorySize, SMEM3);

    // conversions: x split, weights hi-only (fused)
    f2hsplit<<<SEQ * DIM / 1024, 256>>>(x, xh, xl, SEQ * DIM);
    f2h4<<<dim3(QKLD * DIM / 1024, 1, 4), 256>>>(wq, wk, wv, wo, wqh, wkh, wvh, woh);

    // fused QKV projections: A = x (split), B = W (fp16), split-fp16 out
    hgemm_qkv<<<dim3(24, 16, 3), 256, SMEM3>>>(
        xh, xl, wqh, wkh, wvh, qh, ql, kh, kl, vh, vl);

    // RoPE
    rope_kernel<<<(SEQ * NH * 32 + 255) / 256, 256>>>(qh, ql, kh, kl, fc, fs);

    // fused V transpose -> [DIM][SEQ] K-major for PV
    transpose_h2<<<dim3(64, 64, 2), dim3(32, 8)>>>(vh, vth, vl, vtl);

    // scores (causal block skip): A = q (split), B = k hi, fp32 out
    hgemm<1,0,1,0,0><<<dim3(SEQ / 128, SEQ / 128, NH), 256, SMEM3>>>(
        qh, ql, kh, nullptr, sc, nullptr, HD, QKLD, QKLD, SEQ,
        HD, HD, (long long)SEQ * SEQ);

    // softmax -> fp16 probs
    softmax_causal<<<dim3(SEQ, NH), 256>>>(sc, p, rsqrtf((float)HD));

    // PV (causal K-limit): A = probs (single), B = V (split)
    hgemm<0,1,0,1,1><<<dim3(1, SEQ / 128, NH), 256, SMEM3>>>(
        p, nullptr, vth, vtl, oh, ol, SEQ, SEQ, SEQ, DIM,
        (long long)SEQ * SEQ, (long long)VD * SEQ, VD);

    // output projection: A = o (split), B = wo hi, fp32 out
    hgemm<1,0,0,0,0><<<dim3(DIM / 128, SEQ / 128), 256, SMEM3>>>(
        oh, ol, woh, nullptr, out, nullptr, DIM, DIM, DIM, DIM, 0, 0, 0);
}

// round 8
// speedup vs baseline: 1.5051x; 1.2308x over previous
#include <cuda_runtime.h>
#include <cuda_fp16.h>
#include <cstdint>
#include <math.h>

#define SEQ 2048
#define DIM 2048
#define NH 16
#define HD 192
#define NOPE 128
#define ROPE 64
#define VD 128
#define QKLD (NH*HD)   // 3072

// ---------------------------------------------------------------------------
// scratch (allocation-free __device__ globals)
// ---------------------------------------------------------------------------
__device__ __half g_xh [SEQ*DIM];
__device__ __half g_wqh[QKLD*DIM];
__device__ __half g_wkh[QKLD*DIM];
__device__ __half g_wvh[DIM*DIM];
__device__ __half g_woh[DIM*DIM];
__device__ __half g_qh [SEQ*QKLD],  g_ql [SEQ*QKLD];
__device__ __half g_kh [SEQ*QKLD],  g_kl [SEQ*QKLD];
__device__ __half g_vh [SEQ*DIM],   g_vl [SEQ*DIM];
__device__ __half g_vth[DIM*SEQ],   g_vtl[DIM*SEQ];
__device__ float  g_s[(long long)NH*SEQ*SEQ];
__device__ __half g_p[(long long)NH*SEQ*SEQ];
__device__ __half g_oh [SEQ*DIM],   g_ol [SEQ*DIM];

// ---------------------------------------------------------------------------
static __device__ __forceinline__ uint32_t s2u(const void* p) {
    uint32_t a;
    asm("{ .reg .u64 t; cvta.to.shared.u64 t, %1; cvt.u32.u64 %0, t; }" : "=r"(a) : "l"(p));
    return a;
}
#define CPA16(dst, src) \
    asm volatile("cp.async.cg.shared.global [%0], [%1], 16;" :: "r"(dst), "l"(src))
#define CPCOMMIT() asm volatile("cp.async.commit_group;" ::: "memory")
#define CPWAIT1()  asm volatile("cp.async.wait_group 1;" ::: "memory")

#define LDMX4(r0, r1, r2, r3, a) \
    asm volatile("ldmatrix.sync.aligned.m8n8.x4.shared.b16 {%0,%1,%2,%3}, [%4];" \
                 : "=r"(r0), "=r"(r1), "=r"(r2), "=r"(r3) : "r"(a))

#define MMA16816(d, a, b) \
    asm volatile("mma.sync.aligned.m16n8k16.row.col.f32.f16.f16.f32 " \
                 "{%0,%1,%2,%3},{%4,%5,%6,%7},{%8,%9},{%0,%1,%2,%3};" \
                 : "+f"((d)[0]), "+f"((d)[1]), "+f"((d)[2]), "+f"((d)[3]) \
                 : "r"((a)[0]), "r"((a)[1]), "r"((a)[2]), "r"((a)[3]), \
                   "r"((b)[0]), "r"((b)[1]))

// ---------------------------------------------------------------------------
// HMMA GEMM core:  C[tile] = A * B^T  (K-major), 2-term split numerics.
//   acc = Ah*Bh^T  [+ Al*Bh^T if ASPL]  [+ Ah*Bl^T if BSPL]
//   Tile 128x128, 256 threads, warp tile 32x64, 3-stage cp.async pipeline.
//   CHALF: write split-fp16 (Ch,Cl) else fp32.
// ---------------------------------------------------------------------------
template<bool ASPL, bool BSPL, bool CHALF>
static __device__ __forceinline__ void
hgemm_core(const __half* __restrict__ Ahz, const __half* __restrict__ Alz,
           const __half* __restrict__ Bhz, const __half* __restrict__ Blz,
           void* __restrict__ Cv, __half* __restrict__ Cl,
           int m0, int n0, int kend, int lda, int ldb, int ldc)
{
    constexpr int STAGE = (2 + (ASPL ? 1 : 0) + (BSPL ? 1 : 0)) * 10240;
    constexpr int OAL = 10240;
    constexpr int OB  = (ASPL ? 2 : 1) * 10240;
    constexpr int OBL = OB + 10240;

    extern __shared__ __align__(1024) char smem[];
    const uint32_t sb = s2u(smem);

    const int tid = threadIdx.x;
    const int w = tid >> 5, l = tid & 31;
    const int wm = w & 3, wn = w >> 2;

    const int nst = kend >> 5;

    const int lrow = tid >> 2;             // rows lrow, lrow+64
    const int lcb  = (tid & 3) << 4;       // 16B chunk in row

    auto load_tile = [&](const __half* G, int ld, uint32_t dstbase) {
        #pragma unroll
        for (int i = 0; i < 2; i++) {
            const int row = lrow + i * 64;
            CPA16(dstbase + row * 80 + lcb,
                  (const char*)(G + (long long)row * ld) + lcb);
        }
    };

    auto load_stage = [&](int s, int buf) {
        const int k0 = s << 5;
        const uint32_t st = sb + buf * STAGE;
        load_tile(Ahz + (long long)m0 * lda + k0, lda, st);
        if (ASPL) load_tile(Alz + (long long)m0 * lda + k0, lda, st + OAL);
        load_tile(Bhz + (long long)n0 * ldb + k0, ldb, st + OB);
        if (BSPL) load_tile(Blz + (long long)n0 * ldb + k0, ldb, st + OBL);
    };

    float acc[2][8][4];
    #pragma unroll
    for (int i = 0; i < 2; i++)
        #pragma unroll
        for (int j = 0; j < 8; j++)
            #pragma unroll
            for (int c = 0; c < 4; c++) acc[i][j][c] = 0.f;

    // prologue: stages 0,1 in flight
    #pragma unroll
    for (int i = 0; i < 2; i++) {
        if (i < nst) load_stage(i, i);
        CPCOMMIT();
    }

    const int arow = (l & 7) + ((l >> 3) & 1) * 8;
    const int akb0 = ((l >> 4) & 1) * 16;
    const int brow = (l & 7) + ((l >> 4) & 1) * 8;
    const int bkb0 = ((l >> 3) & 1) * 16;

    for (int s = 0; s < nst; s++) {
        CPWAIT1();                 // stage s complete (<=1 group pending)
        __syncthreads();           // all warps done reading buffer (s-1)%3
        if (s + 2 < nst) load_stage(s + 2, (s + 2) % 3);
        CPCOMMIT();                // real or empty: uniform group count

        const uint32_t st = sb + (s % 3) * STAGE;
        #pragma unroll
        for (int kt = 0; kt < 2; kt++) {
            uint32_t b[8][2];
            #pragma unroll
            for (int np = 0; np < 4; np++) {
                const int row = wn * 64 + np * 16 + brow;
                LDMX4(b[np*2][0], b[np*2][1], b[np*2+1][0], b[np*2+1][1],
                      st + OB + row * 80 + kt * 32 + bkb0);
            }
            uint32_t a[2][4];
            #pragma unroll
            for (int mt = 0; mt < 2; mt++) {
                const int row = wm * 32 + mt * 16 + arow;
                LDMX4(a[mt][0], a[mt][1], a[mt][2], a[mt][3],
                      st + row * 80 + kt * 32 + akb0);
            }
            #pragma unroll
            for (int mt = 0; mt < 2; mt++)
                #pragma unroll
                for (int nt = 0; nt < 8; nt++)
                    MMA16816(acc[mt][nt], a[mt], b[nt]);

            if (ASPL) {
                uint32_t a2[2][4];
                #pragma unroll
                for (int mt = 0; mt < 2; mt++) {
                    const int row = wm * 32 + mt * 16 + arow;
                    LDMX4(a2[mt][0], a2[mt][1], a2[mt][2], a2[mt][3],
                          st + OAL + row * 80 + kt * 32 + akb0);
                }
                #pragma unroll
                for (int mt = 0; mt < 2; mt++)
                    #pragma unroll
                    for (int nt = 0; nt < 8; nt++)
                        MMA16816(acc[mt][nt], a2[mt], b[nt]);
            }
            if (BSPL) {
                uint32_t b2[8][2];
                #pragma unroll
                for (int np = 0; np < 4; np++) {
                    const int row = wn * 64 + np * 16 + brow;
                    LDMX4(b2[np*2][0], b2[np*2][1], b2[np*2+1][0], b2[np*2+1][1],
                          st + OBL + row * 80 + kt * 32 + bkb0);
                }
                #pragma unroll
                for (int mt = 0; mt < 2; mt++)
                    #pragma unroll
                    for (int nt = 0; nt < 8; nt++)
                        MMA16816(acc[mt][nt], a[mt], b2[nt]);
            }
        }
    }

    // ----- epilogue -----
    #pragma unroll
    for (int mt = 0; mt < 2; mt++) {
        #pragma unroll
        for (int nt = 0; nt < 8; nt++) {
            const int row = m0 + wm * 32 + mt * 16 + (l >> 2);
            const int col = n0 + wn * 64 + nt * 8 + (l & 3) * 2;
            const float c0 = acc[mt][nt][0], c1 = acc[mt][nt][1];
            const float c2 = acc[mt][nt][2], c3 = acc[mt][nt][3];
            if (CHALF) {
                __half* Ch  = (__half*)Cv;
                __half h0 = __float2half_rn(c0), h1 = __float2half_rn(c1);
                *(__half2*)(Ch + (long long)row * ldc + col) = __halves2half2(h0, h1);
                *(__half2*)(Cl + (long long)row * ldc + col) =
                    __halves2half2(__float2half_rn(c0 - __half2float(h0)),
                                   __float2half_rn(c1 - __half2float(h1)));
                __half h2 = __float2half_rn(c2), h3 = __float2half_rn(c3);
                *(__half2*)(Ch + (long long)(row + 8) * ldc + col) = __halves2half2(h2, h3);
                *(__half2*)(Cl + (long long)(row + 8) * ldc + col) =
                    __halves2half2(__float2half_rn(c2 - __half2float(h2)),
                                   __float2half_rn(c3 - __half2float(h3)));
            } else {
                float* Cf = (float*)Cv;
                *(float2*)(Cf + (long long)row * ldc + col)       = make_float2(c0, c1);
                *(float2*)(Cf + (long long)(row + 8) * ldc + col) = make_float2(c2, c3);
            }
        }
    }
}

// ---------------------------------------------------------------------------
// generic batched GEMM wrapper (scores / PV / WO)
// ---------------------------------------------------------------------------
template<bool ASPL, bool BSPL, bool CSKIP, bool KLIM, bool CHALF>
__global__ void __launch_bounds__(256, 2)
hgemm(const __half* __restrict__ Ah, const __half* __restrict__ Al,
      const __half* __restrict__ Bh, const __half* __restrict__ Bl,
      void* __restrict__ Cv, __half* __restrict__ Cl,
      int K, int lda, int ldb, int ldc,
      long long sA, long long sB, long long sC)
{
    const int m0 = blockIdx.y * 128;
    const int n0 = blockIdx.x * 128;
    if (CSKIP && n0 > m0) return;
    const int kend = KLIM ? min(K, m0 + 128) : K;

    const __half* Ahz = Ah + (long long)blockIdx.z * sA;
    const __half* Alz = ASPL ? Al + (long long)blockIdx.z * sA : nullptr;
    const __half* Bhz = Bh + (long long)blockIdx.z * sB;
    const __half* Blz = BSPL ? Bl + (long long)blockIdx.z * sB : nullptr;
    void*   Cvz = (char*)Cv + (long long)blockIdx.z * sC * (CHALF ? 2 : 4);
    __half* Clz = CHALF ? Cl + (long long)blockIdx.z * sC : nullptr;

    hgemm_core<ASPL, BSPL, CHALF>(Ahz, Alz, Bhz, Blz, Cvz, Clz,
                                  m0, n0, kend, lda, ldb, ldc);
}

// ---------------------------------------------------------------------------
// fused QKV projection (pure fp16 operands): z=0 Q, z=1 K, z=2 V
// ---------------------------------------------------------------------------
__global__ void __launch_bounds__(256, 2)
hgemm_qkv(const __half* __restrict__ xh,
          const __half* __restrict__ wqh, const __half* __restrict__ wkh,
          const __half* __restrict__ wvh,
          __half* __restrict__ qh, __half* __restrict__ ql,
          __half* __restrict__ kh, __half* __restrict__ kl,
          __half* __restrict__ vh, __half* __restrict__ vl)
{
    const int z = blockIdx.z;
    const __half* B; __half *Ch, *Cll; int nb, ldc;
    if (z == 0)      { B = wqh; Ch = qh; Cll = ql; nb = 24; ldc = QKLD; }
    else if (z == 1) { B = wkh; Ch = kh; Cll = kl; nb = 24; ldc = QKLD; }
    else             { B = wvh; Ch = vh; Cll = vl; nb = 16; ldc = DIM;  }
    if ((int)blockIdx.x >= nb) return;

    hgemm_core<false, false, true>(xh, nullptr, B, nullptr, Ch, Cll,
                                   blockIdx.y * 128, blockIdx.x * 128,
                                   DIM, DIM, DIM, ldc);
}

// ---------------------------------------------------------------------------
// fused fp32 -> fp16 (hi only) for x + 4 weight matrices; z selects array
// ---------------------------------------------------------------------------
__global__ void f2h5(const float* __restrict__ x,
                     const float* __restrict__ wq, const float* __restrict__ wk,
                     const float* __restrict__ wv, const float* __restrict__ wo,
                     __half* __restrict__ ox,
                     __half* __restrict__ oq, __half* __restrict__ ok,
                     __half* __restrict__ ov, __half* __restrict__ oo)
{
    const int z = blockIdx.z;
    const float* in; __half* oh; int n;
    if (z == 0)      { in = x;  oh = ox; n = SEQ * DIM; }
    else if (z == 1) { in = wq; oh = oq; n = QKLD * DIM; }
    else if (z == 2) { in = wk; oh = ok; n = QKLD * DIM; }
    else if (z == 3) { in = wv; oh = ov; n = DIM * DIM; }
    else             { in = wo; oh = oo; n = DIM * DIM; }
    int i = (blockIdx.x * 256 + threadIdx.x) * 4;
    if (i >= n) return;
    float4 v = *(const float4*)(in + i);
    *(__half2*)(oh + i)     = __halves2half2(__float2half_rn(v.x), __float2half_rn(v.y));
    *(__half2*)(oh + i + 2) = __halves2half2(__float2half_rn(v.z), __float2half_rn(v.w));
}

// ---------------------------------------------------------------------------
__global__ void rope_kernel(__half* Qh, __half* Ql, __half* Kh, __half* Kl,
                            const float* __restrict__ cosT, const float* __restrict__ sinT)
{
    int idx = blockIdx.x * blockDim.x + threadIdx.x;
    if (idx >= SEQ * NH * (ROPE / 2)) return;
    int i = idx & 31, h = (idx >> 5) & 15, s = idx >> 9;
    float c = cosT[s * 32 + i], sn = sinT[s * 32 + i];
    long long base = (long long)s * QKLD + h * HD + NOPE + 2 * i;
    float a, b, ra, rb; __half hh;
    a = __half2float(Qh[base])   + __half2float(Ql[base]);
    b = __half2float(Qh[base+1]) + __half2float(Ql[base+1]);
    ra = a * c - b * sn; rb = a * sn + b * c;
    hh = __float2half_rn(ra); Qh[base]   = hh; Ql[base]   = __float2half_rn(ra - __half2float(hh));
    hh = __float2half_rn(rb); Qh[base+1] = hh; Ql[base+1] = __float2half_rn(rb - __half2float(hh));
    a = __half2float(Kh[base])   + __half2float(Kl[base]);
    b = __half2float(Kh[base+1]) + __half2float(Kl[base+1]);
    ra = a * c - b * sn; rb = a * sn + b * c;
    hh = __float2half_rn(ra); Kh[base]   = hh; Kl[base]   = __float2half_rn(ra - __half2float(hh));
    hh = __float2half_rn(rb); Kh[base+1] = hh; Kl[base+1] = __float2half_rn(rb - __half2float(hh));
}

// ---------------------------------------------------------------------------
// fused V transpose: z=0 -> (vh->vth), z=1 -> (vl->vtl)
// ---------------------------------------------------------------------------
__global__ void transpose_h2(const __half* __restrict__ in0, __half* __restrict__ out0,
                             const __half* __restrict__ in1, __half* __restrict__ out1)
{
    const __half* in  = blockIdx.z ? in1  : in0;
    __half*       out = blockIdx.z ? out1 : out0;
    __shared__ __half t[32][33];
    int x = blockIdx.x * 32 + threadIdx.x;
    int y = blockIdx.y * 32 + threadIdx.y;
    #pragma unroll
    for (int j = 0; j < 32; j += 8)
        t[threadIdx.y + j][threadIdx.x] = in[(long long)(y + j) * DIM + x];
    __syncthreads();
    x = blockIdx.y * 32 + threadIdx.x;
    y = blockIdx.x * 32 + threadIdx.y;
    #pragma unroll
    for (int j = 0; j < 32; j += 8)
        out[(long long)(y + j) * SEQ + x] = t[threadIdx.x][threadIdx.y + j];
}

// ---------------------------------------------------------------------------
__global__ void softmax_causal(const float* __restrict__ S, __half* __restrict__ P, float scale)
{
    const int s = blockIdx.x, h = blockIdx.y;
    const float* row = S + ((long long)h * SEQ + s) * SEQ;
    __half* prow = P + ((long long)h * SEQ + s) * SEQ;
    const int n = s + 1;
    const int tid = threadIdx.x;
    __shared__ float buf[SEQ];
    __shared__ float red[8];

    float m = -1e30f;
    for (int t = tid; t < n; t += 256) { float v = row[t]; buf[t] = v; m = fmaxf(m, v); }
    #pragma unroll
    for (int o = 16; o; o >>= 1) m = fmaxf(m, __shfl_xor_sync(0xffffffffu, m, o));
    if ((tid & 31) == 0) red[tid >> 5] = m;
    __syncthreads();
    if (tid < 8) {
        float v = red[tid];
        #pragma unroll
        for (int o = 4; o; o >>= 1) v = fmaxf(v, __shfl_xor_sync(0xffu, v, o));
        if (tid == 0) red[0] = v;
    }
    __syncthreads();
    m = red[0];
    __syncthreads();

    float sum = 0.f;
    for (int t = tid; t < n; t += 256) {
        float e = __expf((buf[t] - m) * scale);
        buf[t] = e; sum += e;
    }
    #pragma unroll
    for (int o = 16; o; o >>= 1) sum += __shfl_xor_sync(0xffffffffu, sum, o);
    if ((tid & 31) == 0) red[tid >> 5] = sum;
    __syncthreads();
    if (tid < 8) {
        float v = red[tid];
        #pragma unroll
        for (int o = 4; o; o >>= 1) v += __shfl_xor_sync(0xffu, v, o);
        if (tid == 0) red[0] = v;
    }
    __syncthreads();
    const float inv = 1.f / red[0];
    __syncthreads();

    for (int t = tid * 2; t < SEQ; t += 512) {
        float a = (t     < n) ? buf[t]     * inv : 0.f;
        float b = (t + 1 < n) ? buf[t + 1] * inv : 0.f;
        *(__half2*)(prow + t) = __halves2half2(__float2half_rn(a), __float2half_rn(b));
    }
}

// ---------------------------------------------------------------------------
extern "C" void kernel_launch(void* const* d_in, const int* in_sizes, int n_in,
                              void* d_out, int out_size)
{
    const float* x  = (const float*)d_in[0];
    const float* wq = (const float*)d_in[1];
    const float* wk = (const float*)d_in[2];
    const float* wv = (const float*)d_in[3];
    const float* wo = (const float*)d_in[4];
    const float* fc = (const float*)d_in[5];
    const float* fs = (const float*)d_in[6];
    float* out = (float*)d_out;

    __half *xh, *wqh, *wkh, *wvh, *woh;
    __half *qh, *ql, *kh, *kl, *vh, *vl, *vth, *vtl, *p, *oh, *ol;
    float* sc;
    cudaGetSymbolAddress((void**)&xh, g_xh);
    cudaGetSymbolAddress((void**)&wqh, g_wqh);
    cudaGetSymbolAddress((void**)&wkh, g_wkh);
    cudaGetSymbolAddress((void**)&wvh, g_wvh);
    cudaGetSymbolAddress((void**)&woh, g_woh);
    cudaGetSymbolAddress((void**)&qh, g_qh);   cudaGetSymbolAddress((void**)&ql, g_ql);
    cudaGetSymbolAddress((void**)&kh, g_kh);   cudaGetSymbolAddress((void**)&kl, g_kl);
    cudaGetSymbolAddress((void**)&vh, g_vh);   cudaGetSymbolAddress((void**)&vl, g_vl);
    cudaGetSymbolAddress((void**)&vth, g_vth); cudaGetSymbolAddress((void**)&vtl, g_vtl);
    cudaGetSymbolAddress((void**)&p, g_p);
    cudaGetSymbolAddress((void**)&oh, g_oh);   cudaGetSymbolAddress((void**)&ol, g_ol);
    cudaGetSymbolAddress((void**)&sc, g_s);

    const int SMEM2 = 3 * 20480;  // 61440: pure-fp16 stages (2 tiles)
    const int SMEM3 = 3 * 30720;  // 92160: split stages (3 tiles)
    cudaFuncSetAttribute((const void*)hgemm_qkv,        cudaFuncAttributeMaxDynamicSharedMemorySize, SMEM2);
    cudaFuncSetAttribute((const void*)hgemm<1,0,1,0,0>, cudaFuncAttributeMaxDynamicSharedMemorySize, SMEM3);
    cudaFuncSetAttribute((const void*)hgemm<0,1,0,1,1>, cudaFuncAttributeMaxDynamicSharedMemorySize, SMEM3);
    cudaFuncSetAttribute((const void*)hgemm<1,0,0,0,0>, cudaFuncAttributeMaxDynamicSharedMemorySize, SMEM3);

    // fused conversions: x + 4 weights, fp16 hi only
    f2h5<<<dim3(QKLD * DIM / 1024, 1, 5), 256>>>(x, wq, wk, wv, wo,
                                                 xh, wqh, wkh, wvh, woh);

    // fused QKV projections (pure fp16), split-fp16 outputs
    hgemm_qkv<<<dim3(24, 16, 3), 256, SMEM2>>>(
        xh, wqh, wkh, wvh, qh, ql, kh, kl, vh, vl);

    // RoPE
    rope_kernel<<<(SEQ * NH * 32 + 255) / 256, 256>>>(qh, ql, kh, kl, fc, fs);

    // fused V transpose -> [DIM][SEQ] K-major for PV
    transpose_h2<<<dim3(64, 64, 2), dim3(32, 8)>>>(vh, vth, vl, vtl);

    // scores (causal block skip): A = q (split), B = k hi, fp32 out
    hgemm<1,0,1,0,0><<<dim3(SEQ / 128, SEQ / 128, NH), 256, SMEM3>>>(
        qh, ql, kh, nullptr, sc, nullptr, HD, QKLD, QKLD, SEQ,
        HD, HD, (long long)SEQ * SEQ);

    // softmax -> fp16 probs
    softmax_causal<<<dim3(SEQ, NH), 256>>>(sc, p, rsqrtf((float)HD));

    // PV (causal K-limit): A = probs (single), B = V (split)
    hgemm<0,1,0,1,1><<<dim3(1, SEQ / 128, NH), 256, SMEM3>>>(
        p, nullptr, vth, vtl, oh, ol, SEQ, SEQ, SEQ, DIM,
        (long long)SEQ * SEQ, (long long)VD * SEQ, VD);

    // output projection: A = o (split), B = wo hi, fp32 out
    hgemm<1,0,0,0,0><<<dim3(DIM / 128, SEQ / 128), 256, SMEM3>>>(
        oh, ol, woh, nullptr, out, nullptr, DIM, DIM, DIM, DIM, 0, 0, 0);
}

// round 9
// speedup vs baseline: 1.8166x; 1.2070x over previous
#include <cuda_runtime.h>
#include <cuda_fp16.h>
#include <cstdint>
#include <math.h>

#define SEQ 2048
#define DIM 2048
#define NH 16
#define HD 192
#define NOPE 128
#define ROPE 64
#define VD 128
#define QKLD (NH*HD)   // 3072

// ---------------------------------------------------------------------------
// scratch (allocation-free __device__ globals)
// ---------------------------------------------------------------------------
__device__ __half g_xh [SEQ*DIM];
__device__ __half g_wqh[QKLD*DIM];
__device__ __half g_wkh[QKLD*DIM];
__device__ __half g_wvh[DIM*DIM];
__device__ __half g_woh[DIM*DIM];
__device__ __half g_qh [SEQ*QKLD],  g_ql [SEQ*QKLD];
__device__ __half g_kh [SEQ*QKLD],  g_kl [SEQ*QKLD];
__device__ __half g_vh [SEQ*DIM];
__device__ __half g_vth[DIM*SEQ];
__device__ float  g_s[(long long)NH*SEQ*SEQ];
__device__ __half g_p[(long long)NH*SEQ*SEQ];
__device__ __half g_oh [SEQ*DIM];

// ---------------------------------------------------------------------------
static __device__ __forceinline__ uint32_t s2u(const void* p) {
    uint32_t a;
    asm("{ .reg .u64 t; cvta.to.shared.u64 t, %1; cvt.u32.u64 %0, t; }" : "=r"(a) : "l"(p));
    return a;
}
#define CPA16(dst, src) \
    asm volatile("cp.async.cg.shared.global [%0], [%1], 16;" :: "r"(dst), "l"(src))
#define CPCOMMIT() asm volatile("cp.async.commit_group;" ::: "memory")
#define CPWAIT1()  asm volatile("cp.async.wait_group 1;" ::: "memory")

#define LDMX4(r0, r1, r2, r3, a) \
    asm volatile("ldmatrix.sync.aligned.m8n8.x4.shared.b16 {%0,%1,%2,%3}, [%4];" \
                 : "=r"(r0), "=r"(r1), "=r"(r2), "=r"(r3) : "r"(a))

#define MMA16816(d, a, b) \
    asm volatile("mma.sync.aligned.m16n8k16.row.col.f32.f16.f16.f32 " \
                 "{%0,%1,%2,%3},{%4,%5,%6,%7},{%8,%9},{%0,%1,%2,%3};" \
                 : "+f"((d)[0]), "+f"((d)[1]), "+f"((d)[2]), "+f"((d)[3]) \
                 : "r"((a)[0]), "r"((a)[1]), "r"((a)[2]), "r"((a)[3]), \
                   "r"((b)[0]), "r"((b)[1]))

// ---------------------------------------------------------------------------
// HMMA GEMM core:  C[tile] = A * B^T  (K-major), 2-term split numerics.
//   acc = Ah*Bh^T  [+ Al*Bh^T if ASPL]  [+ Ah*Bl^T if BSPL]
//   Tile 128x128, 256 threads, warp tile 32x64, 3-stage cp.async pipeline.
//   CMODE: 0 = fp32 out, 1 = split-fp16 (Ch,Cl), 2 = fp16 hi only.
// ---------------------------------------------------------------------------
template<bool ASPL, bool BSPL, int CMODE>
static __device__ __forceinline__ void
hgemm_core(const __half* __restrict__ Ahz, const __half* __restrict__ Alz,
           const __half* __restrict__ Bhz, const __half* __restrict__ Blz,
           void* __restrict__ Cv, __half* __restrict__ Cl,
           int m0, int n0, int kend, int lda, int ldb, int ldc)
{
    constexpr int STAGE = (2 + (ASPL ? 1 : 0) + (BSPL ? 1 : 0)) * 10240;
    constexpr int OAL = 10240;
    constexpr int OB  = (ASPL ? 2 : 1) * 10240;
    constexpr int OBL = OB + 10240;

    extern __shared__ __align__(1024) char smem[];
    const uint32_t sb = s2u(smem);

    const int tid = threadIdx.x;
    const int w = tid >> 5, l = tid & 31;
    const int wm = w & 3, wn = w >> 2;

    const int nst = kend >> 5;

    const int lrow = tid >> 2;             // rows lrow, lrow+64
    const int lcb  = (tid & 3) << 4;       // 16B chunk in row

    auto load_tile = [&](const __half* G, int ld, uint32_t dstbase) {
        #pragma unroll
        for (int i = 0; i < 2; i++) {
            const int row = lrow + i * 64;
            CPA16(dstbase + row * 80 + lcb,
                  (const char*)(G + (long long)row * ld) + lcb);
        }
    };

    auto load_stage = [&](int s, int buf) {
        const int k0 = s << 5;
        const uint32_t st = sb + buf * STAGE;
        load_tile(Ahz + (long long)m0 * lda + k0, lda, st);
        if (ASPL) load_tile(Alz + (long long)m0 * lda + k0, lda, st + OAL);
        load_tile(Bhz + (long long)n0 * ldb + k0, ldb, st + OB);
        if (BSPL) load_tile(Blz + (long long)n0 * ldb + k0, ldb, st + OBL);
    };

    float acc[2][8][4];
    #pragma unroll
    for (int i = 0; i < 2; i++)
        #pragma unroll
        for (int j = 0; j < 8; j++)
            #pragma unroll
            for (int c = 0; c < 4; c++) acc[i][j][c] = 0.f;

    // prologue: stages 0,1 in flight
    #pragma unroll
    for (int i = 0; i < 2; i++) {
        if (i < nst) load_stage(i, i);
        CPCOMMIT();
    }

    const int arow = (l & 7) + ((l >> 3) & 1) * 8;
    const int akb0 = ((l >> 4) & 1) * 16;
    const int brow = (l & 7) + ((l >> 4) & 1) * 8;
    const int bkb0 = ((l >> 3) & 1) * 16;

    for (int s = 0; s < nst; s++) {
        CPWAIT1();                 // stage s complete (<=1 group pending)
        __syncthreads();           // all warps done reading buffer (s-1)%3
        if (s + 2 < nst) load_stage(s + 2, (s + 2) % 3);
        CPCOMMIT();                // real or empty: uniform group count

        const uint32_t st = sb + (s % 3) * STAGE;
        #pragma unroll
        for (int kt = 0; kt < 2; kt++) {
            uint32_t b[8][2];
            #pragma unroll
            for (int np = 0; np < 4; np++) {
                const int row = wn * 64 + np * 16 + brow;
                LDMX4(b[np*2][0], b[np*2][1], b[np*2+1][0], b[np*2+1][1],
                      st + OB + row * 80 + kt * 32 + bkb0);
            }
            uint32_t a[2][4];
            #pragma unroll
            for (int mt = 0; mt < 2; mt++) {
                const int row = wm * 32 + mt * 16 + arow;
                LDMX4(a[mt][0], a[mt][1], a[mt][2], a[mt][3],
                      st + row * 80 + kt * 32 + akb0);
            }
            #pragma unroll
            for (int mt = 0; mt < 2; mt++)
                #pragma unroll
                for (int nt = 0; nt < 8; nt++)
                    MMA16816(acc[mt][nt], a[mt], b[nt]);

            if (ASPL) {
                uint32_t a2[2][4];
                #pragma unroll
                for (int mt = 0; mt < 2; mt++) {
                    const int row = wm * 32 + mt * 16 + arow;
                    LDMX4(a2[mt][0], a2[mt][1], a2[mt][2], a2[mt][3],
                          st + OAL + row * 80 + kt * 32 + akb0);
                }
                #pragma unroll
                for (int mt = 0; mt < 2; mt++)
                    #pragma unroll
                    for (int nt = 0; nt < 8; nt++)
                        MMA16816(acc[mt][nt], a2[mt], b[nt]);
            }
            if (BSPL) {
                uint32_t b2[8][2];
                #pragma unroll
                for (int np = 0; np < 4; np++) {
                    const int row = wn * 64 + np * 16 + brow;
                    LDMX4(b2[np*2][0], b2[np*2][1], b2[np*2+1][0], b2[np*2+1][1],
                          st + OBL + row * 80 + kt * 32 + bkb0);
                }
                #pragma unroll
                for (int mt = 0; mt < 2; mt++)
                    #pragma unroll
                    for (int nt = 0; nt < 8; nt++)
                        MMA16816(acc[mt][nt], a[mt], b2[nt]);
            }
        }
    }

    // ----- epilogue -----
    #pragma unroll
    for (int mt = 0; mt < 2; mt++) {
        #pragma unroll
        for (int nt = 0; nt < 8; nt++) {
            const int row = m0 + wm * 32 + mt * 16 + (l >> 2);
            const int col = n0 + wn * 64 + nt * 8 + (l & 3) * 2;
            const float c0 = acc[mt][nt][0], c1 = acc[mt][nt][1];
            const float c2 = acc[mt][nt][2], c3 = acc[mt][nt][3];
            if (CMODE == 1) {
                __half* Ch = (__half*)Cv;
                __half h0 = __float2half_rn(c0), h1 = __float2half_rn(c1);
                *(__half2*)(Ch + (long long)row * ldc + col) = __halves2half2(h0, h1);
                *(__half2*)(Cl + (long long)row * ldc + col) =
                    __halves2half2(__float2half_rn(c0 - __half2float(h0)),
                                   __float2half_rn(c1 - __half2float(h1)));
                __half h2 = __float2half_rn(c2), h3 = __float2half_rn(c3);
                *(__half2*)(Ch + (long long)(row + 8) * ldc + col) = __halves2half2(h2, h3);
                *(__half2*)(Cl + (long long)(row + 8) * ldc + col) =
                    __halves2half2(__float2half_rn(c2 - __half2float(h2)),
                                   __float2half_rn(c3 - __half2float(h3)));
            } else if (CMODE == 2) {
                __half* Ch = (__half*)Cv;
                *(__half2*)(Ch + (long long)row * ldc + col) =
                    __halves2half2(__float2half_rn(c0), __float2half_rn(c1));
                *(__half2*)(Ch + (long long)(row + 8) * ldc + col) =
                    __halves2half2(__float2half_rn(c2), __float2half_rn(c3));
            } else {
                float* Cf = (float*)Cv;
                *(float2*)(Cf + (long long)row * ldc + col)       = make_float2(c0, c1);
                *(float2*)(Cf + (long long)(row + 8) * ldc + col) = make_float2(c2, c3);
            }
        }
    }
}

// ---------------------------------------------------------------------------
// generic batched GEMM wrapper (scores / PV / WO)
// ---------------------------------------------------------------------------
template<bool ASPL, bool BSPL, bool CSKIP, bool KLIM, int CMODE>
__global__ void __launch_bounds__(256, 2)
hgemm(const __half* __restrict__ Ah, const __half* __restrict__ Al,
      const __half* __restrict__ Bh, const __half* __restrict__ Bl,
      void* __restrict__ Cv, __half* __restrict__ Cl,
      int K, int lda, int ldb, int ldc,
      long long sA, long long sB, long long sC)
{
    const int m0 = blockIdx.y * 128;
    const int n0 = blockIdx.x * 128;
    if (CSKIP && n0 > m0) return;
    const int kend = KLIM ? min(K, m0 + 128) : K;

    const __half* Ahz = Ah + (long long)blockIdx.z * sA;
    const __half* Alz = ASPL ? Al + (long long)blockIdx.z * sA : nullptr;
    const __half* Bhz = Bh + (long long)blockIdx.z * sB;
    const __half* Blz = BSPL ? Bl + (long long)blockIdx.z * sB : nullptr;
    void*   Cvz = (char*)Cv + (long long)blockIdx.z * sC * (CMODE == 0 ? 4 : 2);
    __half* Clz = (CMODE == 1) ? Cl + (long long)blockIdx.z * sC : nullptr;

    hgemm_core<ASPL, BSPL, CMODE>(Ahz, Alz, Bhz, Blz, Cvz, Clz,
                                  m0, n0, kend, lda, ldb, ldc);
}

// ---------------------------------------------------------------------------
// fused QKV projection (pure fp16 operands): z=0 Q (split out), z=1 K (split),
// z=2 V (hi only)
// ---------------------------------------------------------------------------
__global__ void __launch_bounds__(256, 2)
hgemm_qkv(const __half* __restrict__ xh,
          const __half* __restrict__ wqh, const __half* __restrict__ wkh,
          const __half* __restrict__ wvh,
          __half* __restrict__ qh, __half* __restrict__ ql,
          __half* __restrict__ kh, __half* __restrict__ kl,
          __half* __restrict__ vh)
{
    const int z = blockIdx.z;
    const int m0 = blockIdx.y * 128;
    const int n0 = blockIdx.x * 128;
    if (z == 2) {
        if ((int)blockIdx.x >= 16) return;
        hgemm_core<false, false, 2>(xh, nullptr, wvh, nullptr, vh, nullptr,
                                    m0, n0, DIM, DIM, DIM, DIM);
    } else {
        const __half* B = z ? wkh : wqh;
        __half* Ch  = z ? kh : qh;
        __half* Cll = z ? kl : ql;
        hgemm_core<false, false, 1>(xh, nullptr, B, nullptr, Ch, Cll,
                                    m0, n0, DIM, DIM, DIM, QKLD);
    }
}

// ---------------------------------------------------------------------------
// fused fp32 -> fp16 (hi only) for x + 4 weight matrices; z selects array
// ---------------------------------------------------------------------------
__global__ void f2h5(const float* __restrict__ x,
                     const float* __restrict__ wq, const float* __restrict__ wk,
                     const float* __restrict__ wv, const float* __restrict__ wo,
                     __half* __restrict__ ox,
                     __half* __restrict__ oq, __half* __restrict__ ok,
                     __half* __restrict__ ov, __half* __restrict__ oo)
{
    const int z = blockIdx.z;
    const float* in; __half* oh; int n;
    if (z == 0)      { in = x;  oh = ox; n = SEQ * DIM; }
    else if (z == 1) { in = wq; oh = oq; n = QKLD * DIM; }
    else if (z == 2) { in = wk; oh = ok; n = QKLD * DIM; }
    else if (z == 3) { in = wv; oh = ov; n = DIM * DIM; }
    else             { in = wo; oh = oo; n = DIM * DIM; }
    int i = (blockIdx.x * 256 + threadIdx.x) * 4;
    if (i >= n) return;
    float4 v = *(const float4*)(in + i);
    *(__half2*)(oh + i)     = __halves2half2(__float2half_rn(v.x), __float2half_rn(v.y));
    *(__half2*)(oh + i + 2) = __halves2half2(__float2half_rn(v.z), __float2half_rn(v.w));
}

// ---------------------------------------------------------------------------
__global__ void rope_kernel(__half* Qh, __half* Ql, __half* Kh, __half* Kl,
                            const float* __restrict__ cosT, const float* __restrict__ sinT)
{
    int idx = blockIdx.x * blockDim.x + threadIdx.x;
    if (idx >= SEQ * NH * (ROPE / 2)) return;
    int i = idx & 31, h = (idx >> 5) & 15, s = idx >> 9;
    float c = cosT[s * 32 + i], sn = sinT[s * 32 + i];
    long long base = (long long)s * QKLD + h * HD + NOPE + 2 * i;
    float a, b, ra, rb; __half hh;
    a = __half2float(Qh[base])   + __half2float(Ql[base]);
    b = __half2float(Qh[base+1]) + __half2float(Ql[base+1]);
    ra = a * c - b * sn; rb = a * sn + b * c;
    hh = __float2half_rn(ra); Qh[base]   = hh; Ql[base]   = __float2half_rn(ra - __half2float(hh));
    hh = __float2half_rn(rb); Qh[base+1] = hh; Ql[base+1] = __float2half_rn(rb - __half2float(hh));
    a = __half2float(Kh[base])   + __half2float(Kl[base]);
    b = __half2float(Kh[base+1]) + __half2float(Kl[base+1]);
    ra = a * c - b * sn; rb = a * sn + b * c;
    hh = __float2half_rn(ra); Kh[base]   = hh; Kl[base]   = __float2half_rn(ra - __half2float(hh));
    hh = __float2half_rn(rb); Kh[base+1] = hh; Kl[base+1] = __float2half_rn(rb - __half2float(hh));
}

// ---------------------------------------------------------------------------
__global__ void transpose_h(const __half* __restrict__ in, __half* __restrict__ out)
{
    __shared__ __half t[32][33];
    int x = blockIdx.x * 32 + threadIdx.x;
    int y = blockIdx.y * 32 + threadIdx.y;
    #pragma unroll
    for (int j = 0; j < 32; j += 8)
        t[threadIdx.y + j][threadIdx.x] = in[(long long)(y + j) * DIM + x];
    __syncthreads();
    x = blockIdx.y * 32 + threadIdx.x;
    y = blockIdx.x * 32 + threadIdx.y;
    #pragma unroll
    for (int j = 0; j < 32; j += 8)
        out[(long long)(y + j) * SEQ + x] = t[threadIdx.x][threadIdx.y + j];
}

// ---------------------------------------------------------------------------
// causal softmax: fp32 scores -> fp16 probs.
// writes only t < round_up(s+1, 128): PV never reads beyond the row's block.
// ---------------------------------------------------------------------------
__global__ void softmax_causal(const float* __restrict__ S, __half* __restrict__ P, float scale)
{
    const int s = blockIdx.x, h = blockIdx.y;
    const float* row = S + ((long long)h * SEQ + s) * SEQ;
    __half* prow = P + ((long long)h * SEQ + s) * SEQ;
    const int n = s + 1;
    const int wend = ((s >> 7) + 1) << 7;   // write bound (multiple of 128)
    const int tid = threadIdx.x;
    __shared__ float buf[SEQ];
    __shared__ float red[8];

    float m = -1e30f;
    for (int t = tid; t < n; t += 256) { float v = row[t]; buf[t] = v; m = fmaxf(m, v); }
    #pragma unroll
    for (int o = 16; o; o >>= 1) m = fmaxf(m, __shfl_xor_sync(0xffffffffu, m, o));
    if ((tid & 31) == 0) red[tid >> 5] = m;
    __syncthreads();
    if (tid < 8) {
        float v = red[tid];
        #pragma unroll
        for (int o = 4; o; o >>= 1) v = fmaxf(v, __shfl_xor_sync(0xffu, v, o));
        if (tid == 0) red[0] = v;
    }
    __syncthreads();
    m = red[0];
    __syncthreads();

    float sum = 0.f;
    for (int t = tid; t < n; t += 256) {
        float e = __expf((buf[t] - m) * scale);
        buf[t] = e; sum += e;
    }
    #pragma unroll
    for (int o = 16; o; o >>= 1) sum += __shfl_xor_sync(0xffffffffu, sum, o);
    if ((tid & 31) == 0) red[tid >> 5] = sum;
    __syncthreads();
    if (tid < 8) {
        float v = red[tid];
        #pragma unroll
        for (int o = 4; o; o >>= 1) v += __shfl_xor_sync(0xffu, v, o);
        if (tid == 0) red[0] = v;
    }
    __syncthreads();
    const float inv = 1.f / red[0];
    __syncthreads();

    for (int t = tid * 2; t < wend; t += 512) {
        float a = (t     < n) ? buf[t]     * inv : 0.f;
        float b = (t + 1 < n) ? buf[t + 1] * inv : 0.f;
        *(__half2*)(prow + t) = __halves2half2(__float2half_rn(a), __float2half_rn(b));
    }
}

// ---------------------------------------------------------------------------
extern "C" void kernel_launch(void* const* d_in, const int* in_sizes, int n_in,
                              void* d_out, int out_size)
{
    const float* x  = (const float*)d_in[0];
    const float* wq = (const float*)d_in[1];
    const float* wk = (const float*)d_in[2];
    const float* wv = (const float*)d_in[3];
    const float* wo = (const float*)d_in[4];
    const float* fc = (const float*)d_in[5];
    const float* fs = (const float*)d_in[6];
    float* out = (float*)d_out;

    __half *xh, *wqh, *wkh, *wvh, *woh;
    __half *qh, *ql, *kh, *kl, *vh, *vth, *p, *oh;
    float* sc;
    cudaGetSymbolAddress((void**)&xh, g_xh);
    cudaGetSymbolAddress((void**)&wqh, g_wqh);
    cudaGetSymbolAddress((void**)&wkh, g_wkh);
    cudaGetSymbolAddress((void**)&wvh, g_wvh);
    cudaGetSymbolAddress((void**)&woh, g_woh);
    cudaGetSymbolAddress((void**)&qh, g_qh);   cudaGetSymbolAddress((void**)&ql, g_ql);
    cudaGetSymbolAddress((void**)&kh, g_kh);   cudaGetSymbolAddress((void**)&kl, g_kl);
    cudaGetSymbolAddress((void**)&vh, g_vh);
    cudaGetSymbolAddress((void**)&vth, g_vth);
    cudaGetSymbolAddress((void**)&p, g_p);
    cudaGetSymbolAddress((void**)&oh, g_oh);
    cudaGetSymbolAddress((void**)&sc, g_s);

    const int SMEM2 = 3 * 20480;  // 61440: pure-fp16 stages (2 tiles)
    const int SMEM3 = 3 * 30720;  // 92160: split stages (3 tiles)
    cudaFuncSetAttribute((const void*)hgemm_qkv,        cudaFuncAttributeMaxDynamicSharedMemorySize, SMEM2);
    cudaFuncSetAttribute((const void*)hgemm<1,0,1,0,0>, cudaFuncAttributeMaxDynamicSharedMemorySize, SMEM3);
    cudaFuncSetAttribute((const void*)hgemm<0,0,0,1,2>, cudaFuncAttributeMaxDynamicSharedMemorySize, SMEM2);
    cudaFuncSetAttribute((const void*)hgemm<0,0,0,0,0>, cudaFuncAttributeMaxDynamicSharedMemorySize, SMEM2);

    // fused conversions: x + 4 weights, fp16 hi only
    f2h5<<<dim3(QKLD * DIM / 1024, 1, 5), 256>>>(x, wq, wk, wv, wo,
                                                 xh, wqh, wkh, wvh, woh);

    // fused QKV projections: Q,K split-fp16 out; V hi-only
    hgemm_qkv<<<dim3(24, 16, 3), 256, SMEM2>>>(
        xh, wqh, wkh, wvh, qh, ql, kh, kl, vh);

    // RoPE
    rope_kernel<<<(SEQ * NH * 32 + 255) / 256, 256>>>(qh, ql, kh, kl, fc, fs);

    // V transpose -> [DIM][SEQ] K-major for PV
    transpose_h<<<dim3(64, 64), dim3(32, 8)>>>(vh, vth);

    // scores (causal block skip): A = q (split), B = k hi, fp32 out
    hgemm<1,0,1,0,0><<<dim3(SEQ / 128, SEQ / 128, NH), 256, SMEM3>>>(
        qh, ql, kh, nullptr, sc, nullptr, HD, QKLD, QKLD, SEQ,
        HD, HD, (long long)SEQ * SEQ);

    // softmax -> fp16 probs (block-bounded writes)
    softmax_causal<<<dim3(SEQ, NH), 256>>>(sc, p, rsqrtf((float)HD));

    // PV (causal K-limit): pure fp16, O hi-only out
    hgemm<0,0,0,1,2><<<dim3(1, SEQ / 128, NH), 256, SMEM2>>>(
        p, nullptr, vth, nullptr, oh, nullptr, SEQ, SEQ, SEQ, DIM,
        (long long)SEQ * SEQ, (long long)VD * SEQ, VD);

    // output projection: A = o hi, B = wo hi, fp32 out
    hgemm<0,0,0,0,0><<<dim3(DIM / 128, SEQ / 128), 256, SMEM2>>>(
        oh, nullptr, woh, nullptr, out, nullptr, DIM, DIM, DIM, DIM, 0, 0, 0);
}

// round 11
// speedup vs baseline: 1.9751x; 1.0873x over previous
#include <cuda_runtime.h>
#include <cuda_fp16.h>
#include <cstdint>
#include <math.h>

#define SEQ 2048
#define DIM 2048
#define NH 16
#define HD 192
#define NOPE 128
#define ROPE 64
#define VD 128
#define QKLD (NH*HD)   // 3072

// ---------------------------------------------------------------------------
// scratch (allocation-free __device__ globals)
// ---------------------------------------------------------------------------
__device__ __half g_xh [SEQ*DIM];
__device__ __half g_wqh[QKLD*DIM];
__device__ __half g_wkh[QKLD*DIM];
__device__ __half g_wvh[DIM*DIM];
__device__ __half g_woh[DIM*DIM];
__device__ __half g_qh [SEQ*QKLD];
__device__ __half g_kh [SEQ*QKLD];
__device__ __half g_vh [SEQ*DIM];
__device__ __half g_vth[DIM*SEQ];
__device__ float  g_s[(long long)NH*SEQ*SEQ];
__device__ __half g_p[(long long)NH*SEQ*SEQ];
__device__ __half g_oh [SEQ*DIM];

// ---------------------------------------------------------------------------
static __device__ __forceinline__ uint32_t s2u(const void* p) {
    uint32_t a;
    asm("{ .reg .u64 t; cvta.to.shared.u64 t, %1; cvt.u32.u64 %0, t; }" : "=r"(a) : "l"(p));
    return a;
}
static __device__ __forceinline__ uint32_t h2u(__half2 h) {
    uint32_t u;
    *(__half2*)&u = h;
    return u;
}
#define CPA16(dst, src) \
    asm volatile("cp.async.cg.shared.global [%0], [%1], 16;" :: "r"(dst), "l"(src))
#define CPCOMMIT() asm volatile("cp.async.commit_group;" ::: "memory")
#define CPWAIT1()  asm volatile("cp.async.wait_group 1;" ::: "memory")

#define LDMX4(r0, r1, r2, r3, a) \
    asm volatile("ldmatrix.sync.aligned.m8n8.x4.shared.b16 {%0,%1,%2,%3}, [%4];" \
                 : "=r"(r0), "=r"(r1), "=r"(r2), "=r"(r3) : "r"(a))

#define MMA16816(d, a, b) \
    asm volatile("mma.sync.aligned.m16n8k16.row.col.f32.f16.f16.f32 " \
                 "{%0,%1,%2,%3},{%4,%5,%6,%7},{%8,%9},{%0,%1,%2,%3};" \
                 : "+f"((d)[0]), "+f"((d)[1]), "+f"((d)[2]), "+f"((d)[3]) \
                 : "r"((a)[0]), "r"((a)[1]), "r"((a)[2]), "r"((a)[3]), \
                   "r"((b)[0]), "r"((b)[1]))

// ---------------------------------------------------------------------------
// HMMA GEMM core:  C[tile] = A * B^T  (K-major).
//   acc = Ah*Bh^T  [+ Al*Bh^T if ASPL]  [+ Ah*Bl^T if BSPL]
//   Tile 128x128, 256 threads, warp tile 32x64, 3-stage cp.async pipeline.
//   CMODE: 0 = fp32 out, 1 = split-fp16 (Ch,Cl), 2 = fp16 hi only.
// ---------------------------------------------------------------------------
template<bool ASPL, bool BSPL, int CMODE>
static __device__ __forceinline__ void
hgemm_core(const __half* __restrict__ Ahz, const __half* __restrict__ Alz,
           const __half* __restrict__ Bhz, const __half* __restrict__ Blz,
           void* __restrict__ Cv, __half* __restrict__ Cl,
           int m0, int n0, int kend, int lda, int ldb, int ldc)
{
    constexpr int STAGE = (2 + (ASPL ? 1 : 0) + (BSPL ? 1 : 0)) * 10240;
    constexpr int OAL = 10240;
    constexpr int OB  = (ASPL ? 2 : 1) * 10240;
    constexpr int OBL = OB + 10240;

    extern __shared__ __align__(1024) char smem[];
    const uint32_t sb = s2u(smem);

    const int tid = threadIdx.x;
    const int w = tid >> 5, l = tid & 31;
    const int wm = w & 3, wn = w >> 2;

    const int nst = kend >> 5;

    const int lrow = tid >> 2;             // rows lrow, lrow+64
    const int lcb  = (tid & 3) << 4;       // 16B chunk in row

    auto load_tile = [&](const __half* G, int ld, uint32_t dstbase) {
        #pragma unroll
        for (int i = 0; i < 2; i++) {
            const int row = lrow + i * 64;
            CPA16(dstbase + row * 80 + lcb,
                  (const char*)(G + (long long)row * ld) + lcb);
        }
    };

    auto load_stage = [&](int s, int buf) {
        const int k0 = s << 5;
        const uint32_t st = sb + buf * STAGE;
        load_tile(Ahz + (long long)m0 * lda + k0, lda, st);
        if (ASPL) load_tile(Alz + (long long)m0 * lda + k0, lda, st + OAL);
        load_tile(Bhz + (long long)n0 * ldb + k0, ldb, st + OB);
        if (BSPL) load_tile(Blz + (long long)n0 * ldb + k0, ldb, st + OBL);
    };

    float acc[2][8][4];
    #pragma unroll
    for (int i = 0; i < 2; i++)
        #pragma unroll
        for (int j = 0; j < 8; j++)
            #pragma unroll
            for (int c = 0; c < 4; c++) acc[i][j][c] = 0.f;

    // prologue: stages 0,1 in flight
    #pragma unroll
    for (int i = 0; i < 2; i++) {
        if (i < nst) load_stage(i, i);
        CPCOMMIT();
    }

    const int arow = (l & 7) + ((l >> 3) & 1) * 8;
    const int akb0 = ((l >> 4) & 1) * 16;
    const int brow = (l & 7) + ((l >> 4) & 1) * 8;
    const int bkb0 = ((l >> 3) & 1) * 16;

    for (int s = 0; s < nst; s++) {
        CPWAIT1();                 // stage s complete (<=1 group pending)
        __syncthreads();           // all warps done reading buffer (s-1)%3
        if (s + 2 < nst) load_stage(s + 2, (s + 2) % 3);
        CPCOMMIT();                // real or empty: uniform group count

        const uint32_t st = sb + (s % 3) * STAGE;
        #pragma unroll
        for (int kt = 0; kt < 2; kt++) {
            uint32_t b[8][2];
            #pragma unroll
            for (int np = 0; np < 4; np++) {
                const int row = wn * 64 + np * 16 + brow;
                LDMX4(b[np*2][0], b[np*2][1], b[np*2+1][0], b[np*2+1][1],
                      st + OB + row * 80 + kt * 32 + bkb0);
            }
            uint32_t a[2][4];
            #pragma unroll
            for (int mt = 0; mt < 2; mt++) {
                const int row = wm * 32 + mt * 16 + arow;
                LDMX4(a[mt][0], a[mt][1], a[mt][2], a[mt][3],
                      st + row * 80 + kt * 32 + akb0);
            }
            #pragma unroll
            for (int mt = 0; mt < 2; mt++)
                #pragma unroll
                for (int nt = 0; nt < 8; nt++)
                    MMA16816(acc[mt][nt], a[mt], b[nt]);

            if (ASPL) {
                uint32_t a2[2][4];
                #pragma unroll
                for (int mt = 0; mt < 2; mt++) {
                    const int row = wm * 32 + mt * 16 + arow;
                    LDMX4(a2[mt][0], a2[mt][1], a2[mt][2], a2[mt][3],
                          st + OAL + row * 80 + kt * 32 + akb0);
                }
                #pragma unroll
                for (int mt = 0; mt < 2; mt++)
                    #pragma unroll
                    for (int nt = 0; nt < 8; nt++)
                        MMA16816(acc[mt][nt], a2[mt], b[nt]);
            }
            if (BSPL) {
                uint32_t b2[8][2];
                #pragma unroll
                for (int np = 0; np < 4; np++) {
                    const int row = wn * 64 + np * 16 + brow;
                    LDMX4(b2[np*2][0], b2[np*2][1], b2[np*2+1][0], b2[np*2+1][1],
                          st + OBL + row * 80 + kt * 32 + bkb0);
                }
                #pragma unroll
                for (int mt = 0; mt < 2; mt++)
                    #pragma unroll
                    for (int nt = 0; nt < 8; nt++)
                        MMA16816(acc[mt][nt], a[mt], b2[nt]);
            }
        }
    }

    // ----- epilogue -----
    #pragma unroll
    for (int mt = 0; mt < 2; mt++) {
        #pragma unroll
        for (int nt = 0; nt < 8; nt++) {
            const int row = m0 + wm * 32 + mt * 16 + (l >> 2);
            const int col = n0 + wn * 64 + nt * 8 + (l & 3) * 2;
            const float c0 = acc[mt][nt][0], c1 = acc[mt][nt][1];
            const float c2 = acc[mt][nt][2], c3 = acc[mt][nt][3];
            if (CMODE == 1) {
                __half* Ch = (__half*)Cv;
                __half h0 = __float2half_rn(c0), h1 = __float2half_rn(c1);
                *(__half2*)(Ch + (long long)row * ldc + col) = __halves2half2(h0, h1);
                *(__half2*)(Cl + (long long)row * ldc + col) =
                    __halves2half2(__float2half_rn(c0 - __half2float(h0)),
                                   __float2half_rn(c1 - __half2float(h1)));
                __half h2 = __float2half_rn(c2), h3 = __float2half_rn(c3);
                *(__half2*)(Ch + (long long)(row + 8) * ldc + col) = __halves2half2(h2, h3);
                *(__half2*)(Cl + (long long)(row + 8) * ldc + col) =
                    __halves2half2(__float2half_rn(c2 - __half2float(h2)),
                                   __float2half_rn(c3 - __half2float(h3)));
            } else if (CMODE == 2) {
                __half* Ch = (__half*)Cv;
                *(__half2*)(Ch + (long long)row * ldc + col) =
                    __halves2half2(__float2half_rn(c0), __float2half_rn(c1));
                *(__half2*)(Ch + (long long)(row + 8) * ldc + col) =
                    __halves2half2(__float2half_rn(c2), __float2half_rn(c3));
            } else {
                float* Cf = (float*)Cv;
                *(float2*)(Cf + (long long)row * ldc + col)       = make_float2(c0, c1);
                *(float2*)(Cf + (long long)(row + 8) * ldc + col) = make_float2(c2, c3);
            }
        }
    }
}

// ---------------------------------------------------------------------------
// generic batched GEMM wrapper (scores / PV / WO)
// ---------------------------------------------------------------------------
template<bool ASPL, bool BSPL, bool CSKIP, bool KLIM, int CMODE>
__global__ void __launch_bounds__(256, 2)
hgemm(const __half* __restrict__ Ah, const __half* __restrict__ Al,
      const __half* __restrict__ Bh, const __half* __restrict__ Bl,
      void* __restrict__ Cv, __half* __restrict__ Cl,
      int K, int lda, int ldb, int ldc,
      long long sA, long long sB, long long sC)
{
    const int m0 = blockIdx.y * 128;
    const int n0 = blockIdx.x * 128;
    if (CSKIP && n0 > m0) return;
    const int kend = KLIM ? min(K, m0 + 128) : K;

    const __half* Ahz = Ah + (long long)blockIdx.z * sA;
    const __half* Alz = ASPL ? Al + (long long)blockIdx.z * sA : nullptr;
    const __half* Bhz = Bh + (long long)blockIdx.z * sB;
    const __half* Blz = BSPL ? Bl + (long long)blockIdx.z * sB : nullptr;
    void*   Cvz = (char*)Cv + (long long)blockIdx.z * sC * (CMODE == 0 ? 4 : 2);
    __half* Clz = (CMODE == 1) ? Cl + (long long)blockIdx.z * sC : nullptr;

    hgemm_core<ASPL, BSPL, CMODE>(Ahz, Alz, Bhz, Blz, Cvz, Clz,
                                  m0, n0, kend, lda, ldb, ldc);
}

// ---------------------------------------------------------------------------
// fused QKV projection (pure fp16 everywhere): z=0 Q, z=1 K, z=2 V
// ---------------------------------------------------------------------------
__global__ void __launch_bounds__(256, 2)
hgemm_qkv(const __half* __restrict__ xh,
          const __half* __restrict__ wqh, const __half* __restrict__ wkh,
          const __half* __restrict__ wvh,
          __half* __restrict__ qh, __half* __restrict__ kh,
          __half* __restrict__ vh)
{
    const int z = blockIdx.z;
    const __half* B; __half* Ch; int nb, ldc;
    if (z == 0)      { B = wqh; Ch = qh; nb = 24; ldc = QKLD; }
    else if (z == 1) { B = wkh; Ch = kh; nb = 24; ldc = QKLD; }
    else             { B = wvh; Ch = vh; nb = 16; ldc = DIM;  }
    if ((int)blockIdx.x >= nb) return;

    hgemm_core<false, false, 2>(xh, nullptr, B, nullptr, Ch, nullptr,
                                blockIdx.y * 128, blockIdx.x * 128,
                                DIM, DIM, DIM, ldc);
}

// ---------------------------------------------------------------------------
// fused fp32 -> fp16 (hi only) for x + 4 weight matrices; z selects array
// ---------------------------------------------------------------------------
__global__ void f2h5(const float* __restrict__ x,
                     const float* __restrict__ wq, const float* __restrict__ wk,
                     const float* __restrict__ wv, const float* __restrict__ wo,
                     __half* __restrict__ ox,
                     __half* __restrict__ oq, __half* __restrict__ ok,
                     __half* __restrict__ ov, __half* __restrict__ oo)
{
    const int z = blockIdx.z;
    const float* in; __half* oh; int n;
    if (z == 0)      { in = x;  oh = ox; n = SEQ * DIM; }
    else if (z == 1) { in = wq; oh = oq; n = QKLD * DIM; }
    else if (z == 2) { in = wk; oh = ok; n = QKLD * DIM; }
    else if (z == 3) { in = wv; oh = ov; n = DIM * DIM; }
    else             { in = wo; oh = oo; n = DIM * DIM; }
    int i = (blockIdx.x * 256 + threadIdx.x) * 4;
    if (i >= n) return;
    float4 v = *(const float4*)(in + i);
    *(__half2*)(oh + i)     = __halves2half2(__float2half_rn(v.x), __float2half_rn(v.y));
    *(__half2*)(oh + i + 2) = __halves2half2(__float2half_rn(v.z), __float2half_rn(v.w));
}

// ---------------------------------------------------------------------------
// RoPE on pe slices of q, k (hi-only, half2 vectorized)
// ---------------------------------------------------------------------------
__global__ void rope_kernel(__half* __restrict__ Qh, __half* __restrict__ Kh,
                            const float* __restrict__ cosT, const float* __restrict__ sinT)
{
    int idx = blockIdx.x * blockDim.x + threadIdx.x;
    if (idx >= SEQ * NH * (ROPE / 2)) return;
    int i = idx & 31, h = (idx >> 5) & 15, s = idx >> 9;
    float c = cosT[s * 32 + i], sn = sinT[s * 32 + i];
    long long base = (long long)s * QKLD + h * HD + NOPE + 2 * i;
    __half2 q = *(__half2*)(Qh + base);
    float a = __half2float(__low2half(q)), b = __half2float(__high2half(q));
    *(__half2*)(Qh + base) = __halves2half2(__float2half_rn(a * c - b * sn),
                                            __float2half_rn(a * sn + b * c));
    __half2 k = *(__half2*)(Kh + base);
    a = __half2float(__low2half(k)); b = __half2float(__high2half(k));
    *(__half2*)(Kh + base) = __halves2half2(__float2half_rn(a * c - b * sn),
                                            __float2half_rn(a * sn + b * c));
}

// ---------------------------------------------------------------------------
__global__ void transpose_h(const __half* __restrict__ in, __half* __restrict__ out)
{
    __shared__ __half t[32][33];
    int x = blockIdx.x * 32 + threadIdx.x;
    int y = blockIdx.y * 32 + threadIdx.y;
    #pragma unroll
    for (int j = 0; j < 32; j += 8)
        t[threadIdx.y + j][threadIdx.x] = in[(long long)(y + j) * DIM + x];
    __syncthreads();
    x = blockIdx.y * 32 + threadIdx.x;
    y = blockIdx.x * 32 + threadIdx.y;
    #pragma unroll
    for (int j = 0; j < 32; j += 8)
        out[(long long)(y + j) * SEQ + x] = t[threadIdx.x][threadIdx.y + j];
}

// ---------------------------------------------------------------------------
// causal softmax: fp32 scores -> fp16 probs, float4/uint4 vectorized.
// reads/writes only t < round_up(s+1, 128) (all written by scores kernel;
// t in [n, wend) is finite garbage, masked out of the reduction).
// ---------------------------------------------------------------------------
__global__ void softmax_causal(const float* __restrict__ S, __half* __restrict__ P, float scale)
{
    const int s = blockIdx.x, h = blockIdx.y;
    const float* row = S + ((long long)h * SEQ + s) * SEQ;
    __half* prow = P + ((long long)h * SEQ + s) * SEQ;
    const int n = s + 1;
    const int wend = ((s >> 7) + 1) << 7;   // multiple of 128
    const int tid = threadIdx.x;
    __shared__ float buf[SEQ];
    __shared__ float red[8];

    float m = -1e30f;
    for (int t = tid * 4; t < wend; t += 1024) {
        float4 v = *(const float4*)(row + t);
        *(float4*)(buf + t) = v;
        if (t     < n) m = fmaxf(m, v.x);
        if (t + 1 < n) m = fmaxf(m, v.y);
        if (t + 2 < n) m = fmaxf(m, v.z);
        if (t + 3 < n) m = fmaxf(m, v.w);
    }
    #pragma unroll
    for (int o = 16; o; o >>= 1) m = fmaxf(m, __shfl_xor_sync(0xffffffffu, m, o));
    if ((tid & 31) == 0) red[tid >> 5] = m;
    __syncthreads();
    if (tid < 8) {
        float v = red[tid];
        #pragma unroll
        for (int o = 4; o; o >>= 1) v = fmaxf(v, __shfl_xor_sync(0xffu, v, o));
        if (tid == 0) red[0] = v;
    }
    __syncthreads();
    m = red[0];
    __syncthreads();

    float sum = 0.f;
    for (int t = tid * 4; t < wend; t += 1024) {
        float4 v = *(const float4*)(buf + t);
        float e0 = (t     < n) ? __expf((v.x - m) * scale) : 0.f;
        float e1 = (t + 1 < n) ? __expf((v.y - m) * scale) : 0.f;
        float e2 = (t + 2 < n) ? __expf((v.z - m) * scale) : 0.f;
        float e3 = (t + 3 < n) ? __expf((v.w - m) * scale) : 0.f;
        *(float4*)(buf + t) = make_float4(e0, e1, e2, e3);
        sum += e0 + e1 + e2 + e3;
    }
    #pragma unroll
    for (int o = 16; o; o >>= 1) sum += __shfl_xor_sync(0xffffffffu, sum, o);
    if ((tid & 31) == 0) red[tid >> 5] = sum;
    __syncthreads();
    if (tid < 8) {
        float v = red[tid];
        #pragma unroll
        for (int o = 4; o; o >>= 1) v += __shfl_xor_sync(0xffu, v, o);
        if (tid == 0) red[0] = v;
    }
    __syncthreads();
    const float inv = 1.f / red[0];
    __syncthreads();

    for (int t = tid * 8; t < wend; t += 2048) {
        float4 a = *(const float4*)(buf + t);
        float4 b = *(const float4*)(buf + t + 4);
        uint4 o;
        o.x = h2u(__halves2half2(__float2half_rn(a.x * inv), __float2half_rn(a.y * inv)));
        o.y = h2u(__halves2half2(__float2half_rn(a.z * inv), __float2half_rn(a.w * inv)));
        o.z = h2u(__halves2half2(__float2half_rn(b.x * inv), __float2half_rn(b.y * inv)));
        o.w = h2u(__halves2half2(__float2half_rn(b.z * inv), __float2half_rn(b.w * inv)));
        *(uint4*)(prow + t) = o;
    }
}

// ---------------------------------------------------------------------------
extern "C" void kernel_launch(void* const* d_in, const int* in_sizes, int n_in,
                              void* d_out, int out_size)
{
    const float* x  = (const float*)d_in[0];
    const float* wq = (const float*)d_in[1];
    const float* wk = (const float*)d_in[2];
    const float* wv = (const float*)d_in[3];
    const float* wo = (const float*)d_in[4];
    const float* fc = (const float*)d_in[5];
    const float* fs = (const float*)d_in[6];
    float* out = (float*)d_out;

    __half *xh, *wqh, *wkh, *wvh, *woh;
    __half *qh, *kh, *vh, *vth, *p, *oh;
    float* sc;
    cudaGetSymbolAddress((void**)&xh, g_xh);
    cudaGetSymbolAddress((void**)&wqh, g_wqh);
    cudaGetSymbolAddress((void**)&wkh, g_wkh);
    cudaGetSymbolAddress((void**)&wvh, g_wvh);
    cudaGetSymbolAddress((void**)&woh, g_woh);
    cudaGetSymbolAddress((void**)&qh, g_qh);
    cudaGetSymbolAddress((void**)&kh, g_kh);
    cudaGetSymbolAddress((void**)&vh, g_vh);
    cudaGetSymbolAddress((void**)&vth, g_vth);
    cudaGetSymbolAddress((void**)&p, g_p);
    cudaGetSymbolAddress((void**)&oh, g_oh);
    cudaGetSymbolAddress((void**)&sc, g_s);

    const int SMEM2 = 3 * 20480;  // 61440: pure-fp16 stages (2 tiles)
    cudaFuncSetAttribute((const void*)hgemm_qkv,        cudaFuncAttributeMaxDynamicSharedMemorySize, SMEM2);
    cudaFuncSetAttribute((const void*)hgemm<0,0,1,0,0>, cudaFuncAttributeMaxDynamicSharedMemorySize, SMEM2);
    cudaFuncSetAttribute((const void*)hgemm<0,0,0,1,2>, cudaFuncAttributeMaxDynamicSharedMemorySize, SMEM2);
    cudaFuncSetAttribute((const void*)hgemm<0,0,0,0,0>, cudaFuncAttributeMaxDynamicSharedMemorySize, SMEM2);

    // fused conversions: x + 4 weights, fp16 hi only
    f2h5<<<dim3(QKLD * DIM / 1024, 1, 5), 256>>>(x, wq, wk, wv, wo,
                                                 xh, wqh, wkh, wvh, woh);

    // fused QKV projections, all fp16 hi-only out
    hgemm_qkv<<<dim3(24, 16, 3), 256, SMEM2>>>(xh, wqh, wkh, wvh, qh, kh, vh);

    // RoPE (hi-only, half2)
    rope_kernel<<<(SEQ * NH * 32 + 255) / 256, 256>>>(qh, kh, fc, fs);

    // V transpose -> [DIM][SEQ] K-major for PV
    transpose_h<<<dim3(64, 64), dim3(32, 8)>>>(vh, vth);

    // scores (causal block skip): pure fp16, fp32 out
    hgemm<0,0,1,0,0><<<dim3(SEQ / 128, SEQ / 128, NH), 256, SMEM2>>>(
        qh, nullptr, kh, nullptr, sc, nullptr, HD, QKLD, QKLD, SEQ,
        HD, HD, (long long)SEQ * SEQ);

    // softmax -> fp16 probs (block-bounded, vectorized)
    softmax_causal<<<dim3(SEQ, NH), 256>>>(sc, p, rsqrtf((float)HD));

    // PV (causal K-limit): pure fp16, O hi-only out
    hgemm<0,0,0,1,2><<<dim3(1, SEQ / 128, NH), 256, SMEM2>>>(
        p, nullptr, vth, nullptr, oh, nullptr, SEQ, SEQ, SEQ, DIM,
        (long long)SEQ * SEQ, (long long)VD * SEQ, VD);

    // output projection: fp16 in, fp32 out
    hgemm<0,0,0,0,0><<<dim3(DIM / 128, SEQ / 128), 256, SMEM2>>>(
        oh, nullptr, woh, nullptr, out, nullptr, DIM, DIM, DIM, DIM, 0, 0, 0);
}

// round 12
// speedup vs baseline: 2.0508x; 1.0383x over previous
#include <cuda_runtime.h>
#include <cuda_fp16.h>
#include <cstdint>
#include <math.h>

#define SEQ 2048
#define DIM 2048
#define NH 16
#define HD 192
#define NOPE 128
#define ROPE 64
#define VD 128
#define QKLD (NH*HD)   // 3072

// ---------------------------------------------------------------------------
// scratch (allocation-free __device__ globals)
// ---------------------------------------------------------------------------
__device__ __half g_xh [SEQ*DIM];
__device__ __half g_wqh[QKLD*DIM];
__device__ __half g_wkh[QKLD*DIM];
__device__ __half g_wvh[DIM*DIM];
__device__ __half g_woh[DIM*DIM];
__device__ __half g_qh [SEQ*QKLD];
__device__ __half g_kh [SEQ*QKLD];
__device__ __half g_vh [SEQ*DIM];
__device__ __half g_vth[DIM*SEQ];
__device__ __half g_s[(long long)NH*SEQ*SEQ];   // fp16 scores
__device__ __half g_p[(long long)NH*SEQ*SEQ];
__device__ __half g_oh [SEQ*DIM];

// ---------------------------------------------------------------------------
static __device__ __forceinline__ uint32_t s2u(const void* p) {
    uint32_t a;
    asm("{ .reg .u64 t; cvta.to.shared.u64 t, %1; cvt.u32.u64 %0, t; }" : "=r"(a) : "l"(p));
    return a;
}
static __device__ __forceinline__ uint32_t h2u(__half2 h) {
    uint32_t u;
    *(__half2*)&u = h;
    return u;
}
#define CPA16(dst, src) \
    asm volatile("cp.async.cg.shared.global [%0], [%1], 16;" :: "r"(dst), "l"(src))
#define CPCOMMIT() asm volatile("cp.async.commit_group;" ::: "memory")
#define CPWAIT1()  asm volatile("cp.async.wait_group 1;" ::: "memory")

#define LDMX4(r0, r1, r2, r3, a) \
    asm volatile("ldmatrix.sync.aligned.m8n8.x4.shared.b16 {%0,%1,%2,%3}, [%4];" \
                 : "=r"(r0), "=r"(r1), "=r"(r2), "=r"(r3) : "r"(a))

#define MMA16816(d, a, b) \
    asm volatile("mma.sync.aligned.m16n8k16.row.col.f32.f16.f16.f32 " \
                 "{%0,%1,%2,%3},{%4,%5,%6,%7},{%8,%9},{%0,%1,%2,%3};" \
                 : "+f"((d)[0]), "+f"((d)[1]), "+f"((d)[2]), "+f"((d)[3]) \
                 : "r"((a)[0]), "r"((a)[1]), "r"((a)[2]), "r"((a)[3]), \
                   "r"((b)[0]), "r"((b)[1]))

// ---------------------------------------------------------------------------
// HMMA GEMM core:  C[tile] = A * B^T  (K-major), pure fp16 operands.
//   Tile 128x128, 256 threads, warp tile 32x64, 3-stage cp.async pipeline.
//   CMODE: 0 = fp32 out, 2 = fp16 out.
// ---------------------------------------------------------------------------
template<int CMODE>
static __device__ __forceinline__ void
hgemm_core(const __half* __restrict__ Ahz, const __half* __restrict__ Bhz,
           void* __restrict__ Cv,
           int m0, int n0, int kend, int lda, int ldb, int ldc)
{
    constexpr int STAGE = 2 * 10240;
    constexpr int OB = 10240;

    extern __shared__ __align__(1024) char smem[];
    const uint32_t sb = s2u(smem);

    const int tid = threadIdx.x;
    const int w = tid >> 5, l = tid & 31;
    const int wm = w & 3, wn = w >> 2;

    const int nst = kend >> 5;

    const int lrow = tid >> 2;             // rows lrow, lrow+64
    const int lcb  = (tid & 3) << 4;       // 16B chunk in row

    auto load_tile = [&](const __half* G, int ld, uint32_t dstbase) {
        #pragma unroll
        for (int i = 0; i < 2; i++) {
            const int row = lrow + i * 64;
            CPA16(dstbase + row * 80 + lcb,
                  (const char*)(G + (long long)row * ld) + lcb);
        }
    };

    auto load_stage = [&](int s, int buf) {
        const int k0 = s << 5;
        const uint32_t st = sb + buf * STAGE;
        load_tile(Ahz + (long long)m0 * lda + k0, lda, st);
        load_tile(Bhz + (long long)n0 * ldb + k0, ldb, st + OB);
    };

    float acc[2][8][4];
    #pragma unroll
    for (int i = 0; i < 2; i++)
        #pragma unroll
        for (int j = 0; j < 8; j++)
            #pragma unroll
            for (int c = 0; c < 4; c++) acc[i][j][c] = 0.f;

    // prologue: stages 0,1 in flight
    #pragma unroll
    for (int i = 0; i < 2; i++) {
        if (i < nst) load_stage(i, i);
        CPCOMMIT();
    }

    const int arow = (l & 7) + ((l >> 3) & 1) * 8;
    const int akb0 = ((l >> 4) & 1) * 16;
    const int brow = (l & 7) + ((l >> 4) & 1) * 8;
    const int bkb0 = ((l >> 3) & 1) * 16;

    for (int s = 0; s < nst; s++) {
        CPWAIT1();                 // stage s complete (<=1 group pending)
        __syncthreads();           // all warps done reading buffer (s-1)%3
        if (s + 2 < nst) load_stage(s + 2, (s + 2) % 3);
        CPCOMMIT();                // real or empty: uniform group count

        const uint32_t st = sb + (s % 3) * STAGE;
        #pragma unroll
        for (int kt = 0; kt < 2; kt++) {
            uint32_t b[8][2];
            #pragma unroll
            for (int np = 0; np < 4; np++) {
                const int row = wn * 64 + np * 16 + brow;
                LDMX4(b[np*2][0], b[np*2][1], b[np*2+1][0], b[np*2+1][1],
                      st + OB + row * 80 + kt * 32 + bkb0);
            }
            uint32_t a[2][4];
            #pragma unroll
            for (int mt = 0; mt < 2; mt++) {
                const int row = wm * 32 + mt * 16 + arow;
                LDMX4(a[mt][0], a[mt][1], a[mt][2], a[mt][3],
                      st + row * 80 + kt * 32 + akb0);
            }
            #pragma unroll
            for (int mt = 0; mt < 2; mt++)
                #pragma unroll
                for (int nt = 0; nt < 8; nt++)
                    MMA16816(acc[mt][nt], a[mt], b[nt]);
        }
    }

    // ----- epilogue -----
    #pragma unroll
    for (int mt = 0; mt < 2; mt++) {
        #pragma unroll
        for (int nt = 0; nt < 8; nt++) {
            const int row = m0 + wm * 32 + mt * 16 + (l >> 2);
            const int col = n0 + wn * 64 + nt * 8 + (l & 3) * 2;
            const float c0 = acc[mt][nt][0], c1 = acc[mt][nt][1];
            const float c2 = acc[mt][nt][2], c3 = acc[mt][nt][3];
            if (CMODE == 2) {
                __half* Ch = (__half*)Cv;
                *(__half2*)(Ch + (long long)row * ldc + col) =
                    __halves2half2(__float2half_rn(c0), __float2half_rn(c1));
                *(__half2*)(Ch + (long long)(row + 8) * ldc + col) =
                    __halves2half2(__float2half_rn(c2), __float2half_rn(c3));
            } else {
                float* Cf = (float*)Cv;
                *(float2*)(Cf + (long long)row * ldc + col)       = make_float2(c0, c1);
                *(float2*)(Cf + (long long)(row + 8) * ldc + col) = make_float2(c2, c3);
            }
        }
    }
}

// ---------------------------------------------------------------------------
// generic batched GEMM wrapper (scores / PV / WO)
// ---------------------------------------------------------------------------
template<bool CSKIP, bool KLIM, int CMODE>
__global__ void __launch_bounds__(256, 2)
hgemm(const __half* __restrict__ Ah, const __half* __restrict__ Bh,
      void* __restrict__ Cv,
      int K, int lda, int ldb, int ldc,
      long long sA, long long sB, long long sC)
{
    const int m0 = blockIdx.y * 128;
    const int n0 = blockIdx.x * 128;
    if (CSKIP && n0 > m0) return;
    const int kend = KLIM ? min(K, m0 + 128) : K;

    const __half* Ahz = Ah + (long long)blockIdx.z * sA;
    const __half* Bhz = Bh + (long long)blockIdx.z * sB;
    void* Cvz = (char*)Cv + (long long)blockIdx.z * sC * (CMODE == 0 ? 4 : 2);

    hgemm_core<CMODE>(Ahz, Bhz, Cvz, m0, n0, kend, lda, ldb, ldc);
}

// ---------------------------------------------------------------------------
// fused QKV projection: z=0 Q, z=1 K, z=2 V
// ---------------------------------------------------------------------------
__global__ void __launch_bounds__(256, 2)
hgemm_qkv(const __half* __restrict__ xh,
          const __half* __restrict__ wqh, const __half* __restrict__ wkh,
          const __half* __restrict__ wvh,
          __half* __restrict__ qh, __half* __restrict__ kh,
          __half* __restrict__ vh)
{
    const int z = blockIdx.z;
    const __half* B; __half* Ch; int nb, ldc;
    if (z == 0)      { B = wqh; Ch = qh; nb = 24; ldc = QKLD; }
    else if (z == 1) { B = wkh; Ch = kh; nb = 24; ldc = QKLD; }
    else             { B = wvh; Ch = vh; nb = 16; ldc = DIM;  }
    if ((int)blockIdx.x >= nb) return;

    hgemm_core<2>(xh, B, Ch, blockIdx.y * 128, blockIdx.x * 128,
                  DIM, DIM, DIM, ldc);
}

// ---------------------------------------------------------------------------
// fused fp32 -> fp16 (hi only), 16 elements/thread; z selects array
// ---------------------------------------------------------------------------
__global__ void f2h5(const float* __restrict__ x,
                     const float* __restrict__ wq, const float* __restrict__ wk,
                     const float* __restrict__ wv, const float* __restrict__ wo,
                     __half* __restrict__ ox,
                     __half* __restrict__ oq, __half* __restrict__ ok,
                     __half* __restrict__ ov, __half* __restrict__ oo)
{
    const int z = blockIdx.z;
    const float* in; __half* oh; int n;
    if (z == 0)      { in = x;  oh = ox; n = SEQ * DIM; }
    else if (z == 1) { in = wq; oh = oq; n = QKLD * DIM; }
    else if (z == 2) { in = wk; oh = ok; n = QKLD * DIM; }
    else if (z == 3) { in = wv; oh = ov; n = DIM * DIM; }
    else             { in = wo; oh = oo; n = DIM * DIM; }
    int i = (blockIdx.x * 256 + threadIdx.x) * 16;
    if (i >= n) return;
    float4 v0 = *(const float4*)(in + i);
    float4 v1 = *(const float4*)(in + i + 4);
    float4 v2 = *(const float4*)(in + i + 8);
    float4 v3 = *(const float4*)(in + i + 12);
    uint4 o0, o1;
    o0.x = h2u(__halves2half2(__float2half_rn(v0.x), __float2half_rn(v0.y)));
    o0.y = h2u(__halves2half2(__float2half_rn(v0.z), __float2half_rn(v0.w)));
    o0.z = h2u(__halves2half2(__float2half_rn(v1.x), __float2half_rn(v1.y)));
    o0.w = h2u(__halves2half2(__float2half_rn(v1.z), __float2half_rn(v1.w)));
    o1.x = h2u(__halves2half2(__float2half_rn(v2.x), __float2half_rn(v2.y)));
    o1.y = h2u(__halves2half2(__float2half_rn(v2.z), __float2half_rn(v2.w)));
    o1.z = h2u(__halves2half2(__float2half_rn(v3.x), __float2half_rn(v3.y)));
    o1.w = h2u(__halves2half2(__float2half_rn(v3.z), __float2half_rn(v3.w)));
    *(uint4*)(oh + i)     = o0;
    *(uint4*)(oh + i + 8) = o1;
}

// ---------------------------------------------------------------------------
// RoPE on pe slices of q, k (hi-only, half2 vectorized)
// ---------------------------------------------------------------------------
__global__ void rope_kernel(__half* __restrict__ Qh, __half* __restrict__ Kh,
                            const float* __restrict__ cosT, const float* __restrict__ sinT)
{
    int idx = blockIdx.x * blockDim.x + threadIdx.x;
    if (idx >= SEQ * NH * (ROPE / 2)) return;
    int i = idx & 31, h = (idx >> 5) & 15, s = idx >> 9;
    float c = cosT[s * 32 + i], sn = sinT[s * 32 + i];
    long long base = (long long)s * QKLD + h * HD + NOPE + 2 * i;
    __half2 q = *(__half2*)(Qh + base);
    float a = __half2float(__low2half(q)), b = __half2float(__high2half(q));
    *(__half2*)(Qh + base) = __halves2half2(__float2half_rn(a * c - b * sn),
                                            __float2half_rn(a * sn + b * c));
    __half2 k = *(__half2*)(Kh + base);
    a = __half2float(__low2half(k)); b = __half2float(__high2half(k));
    *(__half2*)(Kh + base) = __halves2half2(__float2half_rn(a * c - b * sn),
                                            __float2half_rn(a * sn + b * c));
}

// ---------------------------------------------------------------------------
__global__ void transpose_h(const __half* __restrict__ in, __half* __restrict__ out)
{
    __shared__ __half t[32][33];
    int x = blockIdx.x * 32 + threadIdx.x;
    int y = blockIdx.y * 32 + threadIdx.y;
    #pragma unroll
    for (int j = 0; j < 32; j += 8)
        t[threadIdx.y + j][threadIdx.x] = in[(long long)(y + j) * DIM + x];
    __syncthreads();
    x = blockIdx.y * 32 + threadIdx.x;
    y = blockIdx.x * 32 + threadIdx.y;
    #pragma unroll
    for (int j = 0; j < 32; j += 8)
        out[(long long)(y + j) * SEQ + x] = t[threadIdx.x][threadIdx.y + j];
}

// ---------------------------------------------------------------------------
// causal softmax: fp16 scores -> fp16 probs, uint4 vectorized (8 halves/op).
// reads/writes only t < round_up(s+1, 128); [n, wend) is finite garbage,
// masked out of the reduction. fp32 math internally.
// ---------------------------------------------------------------------------
__global__ void softmax_causal(const __half* __restrict__ S, __half* __restrict__ P, float scale)
{
    const int s = blockIdx.x, h = blockIdx.y;
    const __half* row = S + ((long long)h * SEQ + s) * SEQ;
    __half* prow = P + ((long long)h * SEQ + s) * SEQ;
    const int n = s + 1;
    const int wend = ((s >> 7) + 1) << 7;   // multiple of 128
    const int tid = threadIdx.x;
    __shared__ float buf[SEQ];
    __shared__ float red[8];

    float m = -1e30f;
    for (int t = tid * 8; t < wend; t += 2048) {
        uint4 u = *(const uint4*)(row + t);
        float2 f0 = __half22float2(*(__half2*)&u.x);
        float2 f1 = __half22float2(*(__half2*)&u.y);
        float2 f2 = __half22float2(*(__half2*)&u.z);
        float2 f3 = __half22float2(*(__half2*)&u.w);
        buf[t]   = f0.x; buf[t+1] = f0.y; buf[t+2] = f1.x; buf[t+3] = f1.y;
        buf[t+4] = f2.x; buf[t+5] = f2.y; buf[t+6] = f3.x; buf[t+7] = f3.y;
        if (t     < n) m = fmaxf(m, f0.x);
        if (t + 1 < n) m = fmaxf(m, f0.y);
        if (t + 2 < n) m = fmaxf(m, f1.x);
        if (t + 3 < n) m = fmaxf(m, f1.y);
        if (t + 4 < n) m = fmaxf(m, f2.x);
        if (t + 5 < n) m = fmaxf(m, f2.y);
        if (t + 6 < n) m = fmaxf(m, f3.x);
        if (t + 7 < n) m = fmaxf(m, f3.y);
    }
    #pragma unroll
    for (int o = 16; o; o >>= 1) m = fmaxf(m, __shfl_xor_sync(0xffffffffu, m, o));
    if ((tid & 31) == 0) red[tid >> 5] = m;
    __syncthreads();
    if (tid < 8) {
        float v = red[tid];
        #pragma unroll
        for (int o = 4; o; o >>= 1) v = fmaxf(v, __shfl_xor_sync(0xffu, v, o));
        if (tid == 0) red[0] = v;
    }
    __syncthreads();
    m = red[0];
    __syncthreads();

    float sum = 0.f;
    for (int t = tid * 4; t < wend; t += 1024) {
        float4 v = *(const float4*)(buf + t);
        float e0 = (t     < n) ? __expf((v.x - m) * scale) : 0.f;
        float e1 = (t + 1 < n) ? __expf((v.y - m) * scale) : 0.f;
        float e2 = (t + 2 < n) ? __expf((v.z - m) * scale) : 0.f;
        float e3 = (t + 3 < n) ? __expf((v.w - m) * scale) : 0.f;
        *(float4*)(buf + t) = make_float4(e0, e1, e2, e3);
        sum += e0 + e1 + e2 + e3;
    }
    #pragma unroll
    for (int o = 16; o; o >>= 1) sum += __shfl_xor_sync(0xffffffffu, sum, o);
    if ((tid & 31) == 0) red[tid >> 5] = sum;
    __syncthreads();
    if (tid < 8) {
        float v = red[tid];
        #pragma unroll
        for (int o = 4; o; o >>= 1) v += __shfl_xor_sync(0xffu, v, o);
        if (tid == 0) red[0] = v;
    }
    __syncthreads();
    const float inv = 1.f / red[0];
    __syncthreads();

    for (int t = tid * 8; t < wend; t += 2048) {
        float4 a = *(const float4*)(buf + t);
        float4 b = *(const float4*)(buf + t + 4);
        uint4 o;
        o.x = h2u(__halves2half2(__float2half_rn(a.x * inv), __float2half_rn(a.y * inv)));
        o.y = h2u(__halves2half2(__float2half_rn(a.z * inv), __float2half_rn(a.w * inv)));
        o.z = h2u(__halves2half2(__float2half_rn(b.x * inv), __float2half_rn(b.y * inv)));
        o.w = h2u(__halves2half2(__float2half_rn(b.z * inv), __float2half_rn(b.w * inv)));
        *(uint4*)(prow + t) = o;
    }
}

// ---------------------------------------------------------------------------
extern "C" void kernel_launch(void* const* d_in, const int* in_sizes, int n_in,
                              void* d_out, int out_size)
{
    const float* x  = (const float*)d_in[0];
    const float* wq = (const float*)d_in[1];
    const float* wk = (const float*)d_in[2];
    const float* wv = (const float*)d_in[3];
    const float* wo = (const float*)d_in[4];
    const float* fc = (const float*)d_in[5];
    const float* fs = (const float*)d_in[6];
    float* out = (float*)d_out;

    __half *xh, *wqh, *wkh, *wvh, *woh;
    __half *qh, *kh, *vh, *vth, *p, *oh, *sc;
    cudaGetSymbolAddress((void**)&xh, g_xh);
    cudaGetSymbolAddress((void**)&wqh, g_wqh);
    cudaGetSymbolAddress((void**)&wkh, g_wkh);
    cudaGetSymbolAddress((void**)&wvh, g_wvh);
    cudaGetSymbolAddress((void**)&woh, g_woh);
    cudaGetSymbolAddress((void**)&qh, g_qh);
    cudaGetSymbolAddress((void**)&kh, g_kh);
    cudaGetSymbolAddress((void**)&vh, g_vh);
    cudaGetSymbolAddress((void**)&vth, g_vth);
    cudaGetSymbolAddress((void**)&p, g_p);
    cudaGetSymbolAddress((void**)&oh, g_oh);
    cudaGetSymbolAddress((void**)&sc, g_s);

    const int SMEM2 = 3 * 20480;  // 61440: pure-fp16 stages (2 tiles)
    cudaFuncSetAttribute((const void*)hgemm_qkv,    cudaFuncAttributeMaxDynamicSharedMemorySize, SMEM2);
    cudaFuncSetAttribute((const void*)hgemm<1,0,2>, cudaFuncAttributeMaxDynamicSharedMemorySize, SMEM2);
    cudaFuncSetAttribute((const void*)hgemm<0,1,2>, cudaFuncAttributeMaxDynamicSharedMemorySize, SMEM2);
    cudaFuncSetAttribute((const void*)hgemm<0,0,0>, cudaFuncAttributeMaxDynamicSharedMemorySize, SMEM2);

    // fused conversions: x + 4 weights, fp16 hi only (16 elems/thread)
    f2h5<<<dim3(QKLD * DIM / 4096, 1, 5), 256>>>(x, wq, wk, wv, wo,
                                                 xh, wqh, wkh, wvh, woh);

    // fused QKV projections, all fp16 out
    hgemm_qkv<<<dim3(24, 16, 3), 256, SMEM2>>>(xh, wqh, wkh, wvh, qh, kh, vh);

    // RoPE (hi-only, half2)
    rope_kernel<<<(SEQ * NH * 32 + 255) / 256, 256>>>(qh, kh, fc, fs);

    // V transpose -> [DIM][SEQ] K-major for PV
    transpose_h<<<dim3(64, 64), dim3(32, 8)>>>(vh, vth);

    // scores (causal block skip): fp16 in, fp16 out
    hgemm<1,0,2><<<dim3(SEQ / 128, SEQ / 128, NH), 256, SMEM2>>>(
        qh, kh, sc, HD, QKLD, QKLD, SEQ,
        HD, HD, (long long)SEQ * SEQ);

    // softmax: fp16 scores -> fp16 probs (block-bounded, vectorized)
    softmax_causal<<<dim3(SEQ, NH), 256>>>(sc, p, rsqrtf((float)HD));

    // PV (causal K-limit): fp16, O fp16 out
    hgemm<0,1,2><<<dim3(1, SEQ / 128, NH), 256, SMEM2>>>(
        p, vth, oh, SEQ, SEQ, SEQ, DIM,
        (long long)SEQ * SEQ, (long long)VD * SEQ, VD);

    // output projection: fp16 in, fp32 out
    hgemm<0,0,0><<<dim3(DIM / 128, SEQ / 128), 256, SMEM2>>>(
        oh, woh, out, DIM, DIM, DIM, DIM, 0, 0, 0);
}

// round 13
// speedup vs baseline: 2.1908x; 1.0683x over previous
#include <cuda_runtime.h>
#include <cuda_fp16.h>
#include <cstdint>
#include <math.h>

#define SEQ 2048
#define DIM 2048
#define NH 16
#define HD 192
#define NOPE 128
#define ROPE 64
#define VD 128
#define QKLD (NH*HD)   // 3072

// ---------------------------------------------------------------------------
// scratch (allocation-free __device__ globals)
// ---------------------------------------------------------------------------
__device__ __half g_xh [SEQ*DIM];
__device__ __half g_wqh[QKLD*DIM];
__device__ __half g_wkh[QKLD*DIM];
__device__ __half g_wvh[DIM*DIM];
__device__ __half g_woh[DIM*DIM];
__device__ __half g_qh [SEQ*QKLD];
__device__ __half g_kh [SEQ*QKLD];
__device__ __half g_vh [SEQ*DIM];
__device__ __half g_vth[DIM*SEQ];
__device__ __half g_s[(long long)NH*SEQ*SEQ];   // fp16 scores
__device__ __half g_p[(long long)NH*SEQ*SEQ];
__device__ __half g_oh [SEQ*DIM];

// ---------------------------------------------------------------------------
static __device__ __forceinline__ uint32_t s2u(const void* p) {
    uint32_t a;
    asm("{ .reg .u64 t; cvta.to.shared.u64 t, %1; cvt.u32.u64 %0, t; }" : "=r"(a) : "l"(p));
    return a;
}
static __device__ __forceinline__ uint32_t h2u(__half2 h) {
    uint32_t u;
    *(__half2*)&u = h;
    return u;
}
#define CPA16(dst, src) \
    asm volatile("cp.async.cg.shared.global [%0], [%1], 16;" :: "r"(dst), "l"(src))
#define CPCOMMIT() asm volatile("cp.async.commit_group;" ::: "memory")
#define CPWAIT1()  asm volatile("cp.async.wait_group 1;" ::: "memory")

#define LDMX4(r0, r1, r2, r3, a) \
    asm volatile("ldmatrix.sync.aligned.m8n8.x4.shared.b16 {%0,%1,%2,%3}, [%4];" \
                 : "=r"(r0), "=r"(r1), "=r"(r2), "=r"(r3) : "r"(a))

#define MMA16816(d, a, b) \
    asm volatile("mma.sync.aligned.m16n8k16.row.col.f32.f16.f16.f32 " \
                 "{%0,%1,%2,%3},{%4,%5,%6,%7},{%8,%9},{%0,%1,%2,%3};" \
                 : "+f"((d)[0]), "+f"((d)[1]), "+f"((d)[2]), "+f"((d)[3]) \
                 : "r"((a)[0]), "r"((a)[1]), "r"((a)[2]), "r"((a)[3]), \
                   "r"((b)[0]), "r"((b)[1]))

// ---------------------------------------------------------------------------
// HMMA GEMM core:  C[tile] = A * B^T  (K-major), pure fp16 operands.
//   Tile 128x128, 256 threads, warp tile 32x64.
//   K-chunk 64 (row = 128B data + 16B pad = 144B), 3-stage cp.async pipeline.
//   CMODE: 0 = fp32 out, 2 = fp16 out.
// Smem: 3 stages x 2 tiles x 128 rows x 144B = 110592 B.
// ---------------------------------------------------------------------------
template<int CMODE>
static __device__ __forceinline__ void
hgemm_core(const __half* __restrict__ Ahz, const __half* __restrict__ Bhz,
           void* __restrict__ Cv,
           int m0, int n0, int kend, int lda, int ldb, int ldc)
{
    constexpr int ROWB  = 144;          // 128B data + 16B pad
    constexpr int TILE  = 128 * ROWB;   // 18432
    constexpr int STAGE = 2 * TILE;     // 36864

    extern __shared__ __align__(1024) char smem[];
    const uint32_t sb = s2u(smem);

    const int tid = threadIdx.x;
    const int w = tid >> 5, l = tid & 31;
    const int wm = w & 3, wn = w >> 2;

    const int nst = kend >> 6;          // K-chunks of 64

    auto load_tile = [&](const __half* G, int ld, uint32_t dstbase) {
        #pragma unroll
        for (int i = 0; i < 4; i++) {           // 1024 16B-chunks / 256 thr
            const int c = tid + (i << 8);
            const int row = c >> 3;
            const int cb  = (c & 7) << 4;
            CPA16(dstbase + row * ROWB + cb,
                  (const char*)(G + (long long)row * ld) + cb);
        }
    };

    auto load_stage = [&](int s, int buf) {
        const int k0 = s << 6;
        const uint32_t st = sb + buf * STAGE;
        load_tile(Ahz + (long long)m0 * lda + k0, lda, st);
        load_tile(Bhz + (long long)n0 * ldb + k0, ldb, st + TILE);
    };

    float acc[2][8][4];
    #pragma unroll
    for (int i = 0; i < 2; i++)
        #pragma unroll
        for (int j = 0; j < 8; j++)
            #pragma unroll
            for (int c = 0; c < 4; c++) acc[i][j][c] = 0.f;

    // prologue: stages 0,1 in flight
    #pragma unroll
    for (int i = 0; i < 2; i++) {
        if (i < nst) load_stage(i, i);
        CPCOMMIT();
    }

    const int arow = (l & 7) + ((l >> 3) & 1) * 8;
    const int akb0 = ((l >> 4) & 1) * 16;
    const int brow = (l & 7) + ((l >> 4) & 1) * 8;
    const int bkb0 = ((l >> 3) & 1) * 16;

    for (int s = 0; s < nst; s++) {
        CPWAIT1();                 // stage s complete (<=1 group pending)
        __syncthreads();           // all warps done reading buffer (s-1)%3
        if (s + 2 < nst) load_stage(s + 2, (s + 2) % 3);
        CPCOMMIT();                // real or empty: uniform group count

        const uint32_t st = sb + (s % 3) * STAGE;
        #pragma unroll
        for (int kt = 0; kt < 4; kt++) {       // 4 k-steps of 16
            uint32_t b[8][2];
            #pragma unroll
            for (int np = 0; np < 4; np++) {
                const int row = wn * 64 + np * 16 + brow;
                LDMX4(b[np*2][0], b[np*2][1], b[np*2+1][0], b[np*2+1][1],
                      st + TILE + row * ROWB + kt * 32 + bkb0);
            }
            uint32_t a[2][4];
            #pragma unroll
            for (int mt = 0; mt < 2; mt++) {
                const int row = wm * 32 + mt * 16 + arow;
                LDMX4(a[mt][0], a[mt][1], a[mt][2], a[mt][3],
                      st + row * ROWB + kt * 32 + akb0);
            }
            #pragma unroll
            for (int mt = 0; mt < 2; mt++)
                #pragma unroll
                for (int nt = 0; nt < 8; nt++)
                    MMA16816(acc[mt][nt], a[mt], b[nt]);
        }
    }

    // ----- epilogue -----
    #pragma unroll
    for (int mt = 0; mt < 2; mt++) {
        #pragma unroll
        for (int nt = 0; nt < 8; nt++) {
            const int row = m0 + wm * 32 + mt * 16 + (l >> 2);
            const int col = n0 + wn * 64 + nt * 8 + (l & 3) * 2;
            const float c0 = acc[mt][nt][0], c1 = acc[mt][nt][1];
            const float c2 = acc[mt][nt][2], c3 = acc[mt][nt][3];
            if (CMODE == 2) {
                __half* Ch = (__half*)Cv;
                *(__half2*)(Ch + (long long)row * ldc + col) =
                    __halves2half2(__float2half_rn(c0), __float2half_rn(c1));
                *(__half2*)(Ch + (long long)(row + 8) * ldc + col) =
                    __halves2half2(__float2half_rn(c2), __float2half_rn(c3));
            } else {
                float* Cf = (float*)Cv;
                *(float2*)(Cf + (long long)row * ldc + col)       = make_float2(c0, c1);
                *(float2*)(Cf + (long long)(row + 8) * ldc + col) = make_float2(c2, c3);
            }
        }
    }
}

// ---------------------------------------------------------------------------
// generic batched GEMM wrapper (scores / PV / WO)
// ---------------------------------------------------------------------------
template<bool CSKIP, bool KLIM, int CMODE>
__global__ void __launch_bounds__(256, 2)
hgemm(const __half* __restrict__ Ah, const __half* __restrict__ Bh,
      void* __restrict__ Cv,
      int K, int lda, int ldb, int ldc,
      long long sA, long long sB, long long sC)
{
    const int m0 = blockIdx.y * 128;
    const int n0 = blockIdx.x * 128;
    if (CSKIP && n0 > m0) return;
    const int kend = KLIM ? min(K, m0 + 128) : K;

    const __half* Ahz = Ah + (long long)blockIdx.z * sA;
    const __half* Bhz = Bh + (long long)blockIdx.z * sB;
    void* Cvz = (char*)Cv + (long long)blockIdx.z * sC * (CMODE == 0 ? 4 : 2);

    hgemm_core<CMODE>(Ahz, Bhz, Cvz, m0, n0, kend, lda, ldb, ldc);
}

// ---------------------------------------------------------------------------
// fused QKV projection: z=0 Q, z=1 K, z=2 V
// ---------------------------------------------------------------------------
__global__ void __launch_bounds__(256, 2)
hgemm_qkv(const __half* __restrict__ xh,
          const __half* __restrict__ wqh, const __half* __restrict__ wkh,
          const __half* __restrict__ wvh,
          __half* __restrict__ qh, __half* __restrict__ kh,
          __half* __restrict__ vh)
{
    const int z = blockIdx.z;
    const __half* B; __half* Ch; int nb, ldc;
    if (z == 0)      { B = wqh; Ch = qh; nb = 24; ldc = QKLD; }
    else if (z == 1) { B = wkh; Ch = kh; nb = 24; ldc = QKLD; }
    else             { B = wvh; Ch = vh; nb = 16; ldc = DIM;  }
    if ((int)blockIdx.x >= nb) return;

    hgemm_core<2>(xh, B, Ch, blockIdx.y * 128, blockIdx.x * 128,
                  DIM, DIM, DIM, ldc);
}

// ---------------------------------------------------------------------------
// fused fp32 -> fp16 (hi only), 16 elements/thread; z selects array
// ---------------------------------------------------------------------------
__global__ void f2h5(const float* __restrict__ x,
                     const float* __restrict__ wq, const float* __restrict__ wk,
                     const float* __restrict__ wv, const float* __restrict__ wo,
                     __half* __restrict__ ox,
                     __half* __restrict__ oq, __half* __restrict__ ok,
                     __half* __restrict__ ov, __half* __restrict__ oo)
{
    const int z = blockIdx.z;
    const float* in; __half* oh; int n;
    if (z == 0)      { in = x;  oh = ox; n = SEQ * DIM; }
    else if (z == 1) { in = wq; oh = oq; n = QKLD * DIM; }
    else if (z == 2) { in = wk; oh = ok; n = QKLD * DIM; }
    else if (z == 3) { in = wv; oh = ov; n = DIM * DIM; }
    else             { in = wo; oh = oo; n = DIM * DIM; }
    int i = (blockIdx.x * 256 + threadIdx.x) * 16;
    if (i >= n) return;
    float4 v0 = *(const float4*)(in + i);
    float4 v1 = *(const float4*)(in + i + 4);
    float4 v2 = *(const float4*)(in + i + 8);
    float4 v3 = *(const float4*)(in + i + 12);
    uint4 o0, o1;
    o0.x = h2u(__halves2half2(__float2half_rn(v0.x), __float2half_rn(v0.y)));
    o0.y = h2u(__halves2half2(__float2half_rn(v0.z), __float2half_rn(v0.w)));
    o0.z = h2u(__halves2half2(__float2half_rn(v1.x), __float2half_rn(v1.y)));
    o0.w = h2u(__halves2half2(__float2half_rn(v1.z), __float2half_rn(v1.w)));
    o1.x = h2u(__halves2half2(__float2half_rn(v2.x), __float2half_rn(v2.y)));
    o1.y = h2u(__halves2half2(__float2half_rn(v2.z), __float2half_rn(v2.w)));
    o1.z = h2u(__halves2half2(__float2half_rn(v3.x), __float2half_rn(v3.y)));
    o1.w = h2u(__halves2half2(__float2half_rn(v3.z), __float2half_rn(v3.w)));
    *(uint4*)(oh + i)     = o0;
    *(uint4*)(oh + i + 8) = o1;
}

// ---------------------------------------------------------------------------
// RoPE on pe slices of q, k (hi-only, half2 vectorized)
// ---------------------------------------------------------------------------
__global__ void rope_kernel(__half* __restrict__ Qh, __half* __restrict__ Kh,
                            const float* __restrict__ cosT, const float* __restrict__ sinT)
{
    int idx = blockIdx.x * blockDim.x + threadIdx.x;
    if (idx >= SEQ * NH * (ROPE / 2)) return;
    int i = idx & 31, h = (idx >> 5) & 15, s = idx >> 9;
    float c = cosT[s * 32 + i], sn = sinT[s * 32 + i];
    long long base = (long long)s * QKLD + h * HD + NOPE + 2 * i;
    __half2 q = *(__half2*)(Qh + base);
    float a = __half2float(__low2half(q)), b = __half2float(__high2half(q));
    *(__half2*)(Qh + base) = __halves2half2(__float2half_rn(a * c - b * sn),
                                            __float2half_rn(a * sn + b * c));
    __half2 k = *(__half2*)(Kh + base);
    a = __half2float(__low2half(k)); b = __half2float(__high2half(k));
    *(__half2*)(Kh + base) = __halves2half2(__float2half_rn(a * c - b * sn),
                                            __float2half_rn(a * sn + b * c));
}

// ---------------------------------------------------------------------------
__global__ void transpose_h(const __half* __restrict__ in, __half* __restrict__ out)
{
    __shared__ __half t[32][33];
    int x = blockIdx.x * 32 + threadIdx.x;
    int y = blockIdx.y * 32 + threadIdx.y;
    #pragma unroll
    for (int j = 0; j < 32; j += 8)
        t[threadIdx.y + j][threadIdx.x] = in[(long long)(y + j) * DIM + x];
    __syncthreads();
    x = blockIdx.y * 32 + threadIdx.x;
    y = blockIdx.x * 32 + threadIdx.y;
    #pragma unroll
    for (int j = 0; j < 32; j += 8)
        out[(long long)(y + j) * SEQ + x] = t[threadIdx.x][threadIdx.y + j];
}

// ---------------------------------------------------------------------------
// causal softmax: fp16 scores -> fp16 probs, uint4 vectorized (8 halves/op).
// reads/writes only t < round_up(s+1, 128); [n, wend) is finite garbage,
// masked out of the reduction. fp32 math internally.
// ---------------------------------------------------------------------------
__global__ void softmax_causal(const __half* __restrict__ S, __half* __restrict__ P, float scale)
{
    const int s = blockIdx.x, h = blockIdx.y;
    const __half* row = S + ((long long)h * SEQ + s) * SEQ;
    __half* prow = P + ((long long)h * SEQ + s) * SEQ;
    const int n = s + 1;
    const int wend = ((s >> 7) + 1) << 7;   // multiple of 128
    const int tid = threadIdx.x;
    __shared__ float buf[SEQ];
    __shared__ float red[8];

    float m = -1e30f;
    for (int t = tid * 8; t < wend; t += 2048) {
        uint4 u = *(const uint4*)(row + t);
        float2 f0 = __half22float2(*(__half2*)&u.x);
        float2 f1 = __half22float2(*(__half2*)&u.y);
        float2 f2 = __half22float2(*(__half2*)&u.z);
        float2 f3 = __half22float2(*(__half2*)&u.w);
        buf[t]   = f0.x; buf[t+1] = f0.y; buf[t+2] = f1.x; buf[t+3] = f1.y;
        buf[t+4] = f2.x; buf[t+5] = f2.y; buf[t+6] = f3.x; buf[t+7] = f3.y;
        if (t     < n) m = fmaxf(m, f0.x);
        if (t + 1 < n) m = fmaxf(m, f0.y);
        if (t + 2 < n) m = fmaxf(m, f1.x);
        if (t + 3 < n) m = fmaxf(m, f1.y);
        if (t + 4 < n) m = fmaxf(m, f2.x);
        if (t + 5 < n) m = fmaxf(m, f2.y);
        if (t + 6 < n) m = fmaxf(m, f3.x);
        if (t + 7 < n) m = fmaxf(m, f3.y);
    }
    #pragma unroll
    for (int o = 16; o; o >>= 1) m = fmaxf(m, __shfl_xor_sync(0xffffffffu, m, o));
    if ((tid & 31) == 0) red[tid >> 5] = m;
    __syncthreads();
    if (tid < 8) {
        float v = red[tid];
        #pragma unroll
        for (int o = 4; o; o >>= 1) v = fmaxf(v, __shfl_xor_sync(0xffu, v, o));
        if (tid == 0) red[0] = v;
    }
    __syncthreads();
    m = red[0];
    __syncthreads();

    float sum = 0.f;
    for (int t = tid * 4; t < wend; t += 1024) {
        float4 v = *(const float4*)(buf + t);
        float e0 = (t     < n) ? __expf((v.x - m) * scale) : 0.f;
        float e1 = (t + 1 < n) ? __expf((v.y - m) * scale) : 0.f;
        float e2 = (t + 2 < n) ? __expf((v.z - m) * scale) : 0.f;
        float e3 = (t + 3 < n) ? __expf((v.w - m) * scale) : 0.f;
        *(float4*)(buf + t) = make_float4(e0, e1, e2, e3);
        sum += e0 + e1 + e2 + e3;
    }
    #pragma unroll
    for (int o = 16; o; o >>= 1) sum += __shfl_xor_sync(0xffffffffu, sum, o);
    if ((tid & 31) == 0) red[tid >> 5] = sum;
    __syncthreads();
    if (tid < 8) {
        float v = red[tid];
        #pragma unroll
        for (int o = 4; o; o >>= 1) v += __shfl_xor_sync(0xffu, v, o);
        if (tid == 0) red[0] = v;
    }
    __syncthreads();
    const float inv = 1.f / red[0];
    __syncthreads();

    for (int t = tid * 8; t < wend; t += 2048) {
        float4 a = *(const float4*)(buf + t);
        float4 b = *(const float4*)(buf + t + 4);
        uint4 o;
        o.x = h2u(__halves2half2(__float2half_rn(a.x * inv), __float2half_rn(a.y * inv)));
        o.y = h2u(__halves2half2(__float2half_rn(a.z * inv), __float2half_rn(a.w * inv)));
        o.z = h2u(__halves2half2(__float2half_rn(b.x * inv), __float2half_rn(b.y * inv)));
        o.w = h2u(__halves2half2(__float2half_rn(b.z * inv), __float2half_rn(b.w * inv)));
        *(uint4*)(prow + t) = o;
    }
}

// ---------------------------------------------------------------------------
extern "C" void kernel_launch(void* const* d_in, const int* in_sizes, int n_in,
                              void* d_out, int out_size)
{
    const float* x  = (const float*)d_in[0];
    const float* wq = (const float*)d_in[1];
    const float* wk = (const float*)d_in[2];
    const float* wv = (const float*)d_in[3];
    const float* wo = (const float*)d_in[4];
    const float* fc = (const float*)d_in[5];
    const float* fs = (const float*)d_in[6];
    float* out = (float*)d_out;

    __half *xh, *wqh, *wkh, *wvh, *woh;
    __half *qh, *kh, *vh, *vth, *p, *oh, *sc;
    cudaGetSymbolAddress((void**)&xh, g_xh);
    cudaGetSymbolAddress((void**)&wqh, g_wqh);
    cudaGetSymbolAddress((void**)&wkh, g_wkh);
    cudaGetSymbolAddress((void**)&wvh, g_wvh);
    cudaGetSymbolAddress((void**)&woh, g_woh);
    cudaGetSymbolAddress((void**)&qh, g_qh);
    cudaGetSymbolAddress((void**)&kh, g_kh);
    cudaGetSymbolAddress((void**)&vh, g_vh);
    cudaGetSymbolAddress((void**)&vth, g_vth);
    cudaGetSymbolAddress((void**)&p, g_p);
    cudaGetSymbolAddress((void**)&oh, g_oh);
    cudaGetSymbolAddress((void**)&sc, g_s);

    const int SMEM = 3 * 36864;  // 110592: 3 stages x 2 tiles x 128 x 144B
    cudaFuncSetAttribute((const void*)hgemm_qkv,    cudaFuncAttributeMaxDynamicSharedMemorySize, SMEM);
    cudaFuncSetAttribute((const void*)hgemm<1,0,2>, cudaFuncAttributeMaxDynamicSharedMemorySize, SMEM);
    cudaFuncSetAttribute((const void*)hgemm<0,1,2>, cudaFuncAttributeMaxDynamicSharedMemorySize, SMEM);
    cudaFuncSetAttribute((const void*)hgemm<0,0,0>, cudaFuncAttributeMaxDynamicSharedMemorySize, SMEM);

    // fused conversions: x + 4 weights, fp16 hi only (16 elems/thread)
    f2h5<<<dim3(QKLD * DIM / 4096, 1, 5), 256>>>(x, wq, wk, wv, wo,
                                                 xh, wqh, wkh, wvh, woh);

    // fused QKV projections, all fp16 out
    hgemm_qkv<<<dim3(24, 16, 3), 256, SMEM>>>(xh, wqh, wkh, wvh, qh, kh, vh);

    // RoPE (hi-only, half2)
    rope_kernel<<<(SEQ * NH * 32 + 255) / 256, 256>>>(qh, kh, fc, fs);

    // V transpose -> [DIM][SEQ] K-major for PV
    transpose_h<<<dim3(64, 64), dim3(32, 8)>>>(vh, vth);

    // scores (causal block skip): fp16 in, fp16 out; K=192 -> 3 chunks
    hgemm<1,0,2><<<dim3(SEQ / 128, SEQ / 128, NH), 256, SMEM>>>(
        qh, kh, sc, HD, QKLD, QKLD, SEQ,
        HD, HD, (long long)SEQ * SEQ);

    // softmax: fp16 scores -> fp16 probs (block-bounded, vectorized)
    softmax_causal<<<dim3(SEQ, NH), 256>>>(sc, p, rsqrtf((float)HD));

    // PV (causal K-limit): fp16, O fp16 out
    hgemm<0,1,2><<<dim3(1, SEQ / 128, NH), 256, SMEM>>>(
        p, vth, oh, SEQ, SEQ, SEQ, DIM,
        (long long)SEQ * SEQ, (long long)VD * SEQ, VD);

    // output projection: fp16 in, fp32 out
    hgemm<0,0,0><<<dim3(DIM / 128, SEQ / 128), 256, SMEM>>>(
        oh, woh, out, DIM, DIM, DIM, DIM, 0, 0, 0);
}

// round 14
// speedup vs baseline: 2.5042x; 1.1431x over previous
#include <cuda_runtime.h>
#include <cuda_fp16.h>
#include <cstdint>
#include <math.h>

#define SEQ 2048
#define DIM 2048
#define NH 16
#define HD 192
#define NOPE 128
#define ROPE 64
#define VD 128
#define QKLD (NH*HD)   // 3072
#define TBLK 64

// ---------------------------------------------------------------------------
// scratch (allocation-free __device__ globals)
// ---------------------------------------------------------------------------
__device__ __half g_xh [SEQ*DIM];
__device__ __half g_wqh[QKLD*DIM];
__device__ __half g_wkh[QKLD*DIM];
__device__ __half g_wvh[DIM*DIM];
__device__ __half g_woh[DIM*DIM];
__device__ __half g_qh [SEQ*QKLD];
__device__ __half g_kh [SEQ*QKLD];
__device__ __half g_vh [SEQ*DIM];
__device__ __half g_vth[DIM*SEQ];
__device__ __half g_oh [SEQ*DIM];

// ---------------------------------------------------------------------------
static __device__ __forceinline__ uint32_t s2u(const void* p) {
    uint32_t a;
    asm("{ .reg .u64 t; cvta.to.shared.u64 t, %1; cvt.u32.u64 %0, t; }" : "=r"(a) : "l"(p));
    return a;
}
static __device__ __forceinline__ uint32_t h2u(__half2 h) {
    uint32_t u;
    *(__half2*)&u = h;
    return u;
}
#define CPA16(dst, src) \
    asm volatile("cp.async.cg.shared.global [%0], [%1], 16;" :: "r"(dst), "l"(src))
#define CPCOMMIT() asm volatile("cp.async.commit_group;" ::: "memory")
#define CPWAIT1()  asm volatile("cp.async.wait_group 1;" ::: "memory")
#define CPWAIT2()  asm volatile("cp.async.wait_group 2;" ::: "memory")

#define LDMX4(r0, r1, r2, r3, a) \
    asm volatile("ldmatrix.sync.aligned.m8n8.x4.shared.b16 {%0,%1,%2,%3}, [%4];" \
                 : "=r"(r0), "=r"(r1), "=r"(r2), "=r"(r3) : "r"(a))

#define MMA16816(d, a, b) \
    asm volatile("mma.sync.aligned.m16n8k16.row.col.f32.f16.f16.f32 " \
                 "{%0,%1,%2,%3},{%4,%5,%6,%7},{%8,%9},{%0,%1,%2,%3};" \
                 : "+f"((d)[0]), "+f"((d)[1]), "+f"((d)[2]), "+f"((d)[3]) \
                 : "r"((a)[0]), "r"((a)[1]), "r"((a)[2]), "r"((a)[3]), \
                   "r"((b)[0]), "r"((b)[1]))

// ---------------------------------------------------------------------------
// HMMA GEMM core:  C[tile] = A * B^T  (K-major), pure fp16 operands.
//   Tile 128x128, 256 threads, warp tile 32x64.
//   K-chunk 64 (row = 128B data + 16B pad = 144B), 3-stage cp.async pipeline.
//   CMODE: 0 = fp32 out, 2 = fp16 out.
// ---------------------------------------------------------------------------
template<int CMODE>
static __device__ __forceinline__ void
hgemm_core(const __half* __restrict__ Ahz, const __half* __restrict__ Bhz,
           void* __restrict__ Cv,
           int m0, int n0, int kend, int lda, int ldb, int ldc)
{
    constexpr int ROWB  = 144;
    constexpr int TILE  = 128 * ROWB;
    constexpr int STAGE = 2 * TILE;

    extern __shared__ __align__(1024) char smem[];
    const uint32_t sb = s2u(smem);

    const int tid = threadIdx.x;
    const int w = tid >> 5, l = tid & 31;
    const int wm = w & 3, wn = w >> 2;

    const int nst = kend >> 6;

    auto load_tile = [&](const __half* G, int ld, uint32_t dstbase) {
        #pragma unroll
        for (int i = 0; i < 4; i++) {
            const int c = tid + (i << 8);
            const int row = c >> 3;
            const int cb  = (c & 7) << 4;
            CPA16(dstbase + row * ROWB + cb,
                  (const char*)(G + (long long)row * ld) + cb);
        }
    };

    auto load_stage = [&](int s, int buf) {
        const int k0 = s << 6;
        const uint32_t st = sb + buf * STAGE;
        load_tile(Ahz + (long long)m0 * lda + k0, lda, st);
        load_tile(Bhz + (long long)n0 * ldb + k0, ldb, st + TILE);
    };

    float acc[2][8][4];
    #pragma unroll
    for (int i = 0; i < 2; i++)
        #pragma unroll
        for (int j = 0; j < 8; j++)
            #pragma unroll
            for (int c = 0; c < 4; c++) acc[i][j][c] = 0.f;

    #pragma unroll
    for (int i = 0; i < 2; i++) {
        if (i < nst) load_stage(i, i);
        CPCOMMIT();
    }

    const int arow = (l & 7) + ((l >> 3) & 1) * 8;
    const int akb0 = ((l >> 4) & 1) * 16;
    const int brow = (l & 7) + ((l >> 4) & 1) * 8;
    const int bkb0 = ((l >> 3) & 1) * 16;

    for (int s = 0; s < nst; s++) {
        CPWAIT1();
        __syncthreads();
        if (s + 2 < nst) load_stage(s + 2, (s + 2) % 3);
        CPCOMMIT();

        const uint32_t st = sb + (s % 3) * STAGE;
        #pragma unroll
        for (int kt = 0; kt < 4; kt++) {
            uint32_t b[8][2];
            #pragma unroll
            for (int np = 0; np < 4; np++) {
                const int row = wn * 64 + np * 16 + brow;
                LDMX4(b[np*2][0], b[np*2][1], b[np*2+1][0], b[np*2+1][1],
                      st + TILE + row * ROWB + kt * 32 + bkb0);
            }
            uint32_t a[2][4];
            #pragma unroll
            for (int mt = 0; mt < 2; mt++) {
                const int row = wm * 32 + mt * 16 + arow;
                LDMX4(a[mt][0], a[mt][1], a[mt][2], a[mt][3],
                      st + row * ROWB + kt * 32 + akb0);
            }
            #pragma unroll
            for (int mt = 0; mt < 2; mt++)
                #pragma unroll
                for (int nt = 0; nt < 8; nt++)
                    MMA16816(acc[mt][nt], a[mt], b[nt]);
        }
    }

    #pragma unroll
    for (int mt = 0; mt < 2; mt++) {
        #pragma unroll
        for (int nt = 0; nt < 8; nt++) {
            const int row = m0 + wm * 32 + mt * 16 + (l >> 2);
            const int col = n0 + wn * 64 + nt * 8 + (l & 3) * 2;
            const float c0 = acc[mt][nt][0], c1 = acc[mt][nt][1];
            const float c2 = acc[mt][nt][2], c3 = acc[mt][nt][3];
            if (CMODE == 2) {
                __half* Ch = (__half*)Cv;
                *(__half2*)(Ch + (long long)row * ldc + col) =
                    __halves2half2(__float2half_rn(c0), __float2half_rn(c1));
                *(__half2*)(Ch + (long long)(row + 8) * ldc + col) =
                    __halves2half2(__float2half_rn(c2), __float2half_rn(c3));
            } else {
                float* Cf = (float*)Cv;
                *(float2*)(Cf + (long long)row * ldc + col)       = make_float2(c0, c1);
                *(float2*)(Cf + (long long)(row + 8) * ldc + col) = make_float2(c2, c3);
            }
        }
    }
}

// ---------------------------------------------------------------------------
// WO GEMM wrapper
// ---------------------------------------------------------------------------
template<int CMODE>
__global__ void __launch_bounds__(256, 2)
hgemm(const __half* __restrict__ Ah, const __half* __restrict__ Bh,
      void* __restrict__ Cv, int K, int lda, int ldb, int ldc)
{
    hgemm_core<CMODE>(Ah, Bh, Cv, blockIdx.y * 128, blockIdx.x * 128,
                      K, lda, ldb, ldc);
}

// ---------------------------------------------------------------------------
// fused QKV projection: z=0 Q, z=1 K, z=2 V
// ---------------------------------------------------------------------------
__global__ void __launch_bounds__(256, 2)
hgemm_qkv(const __half* __restrict__ xh,
          const __half* __restrict__ wqh, const __half* __restrict__ wkh,
          const __half* __restrict__ wvh,
          __half* __restrict__ qh, __half* __restrict__ kh,
          __half* __restrict__ vh)
{
    const int z = blockIdx.z;
    const __half* B; __half* Ch; int nb, ldc;
    if (z == 0)      { B = wqh; Ch = qh; nb = 24; ldc = QKLD; }
    else if (z == 1) { B = wkh; Ch = kh; nb = 24; ldc = QKLD; }
    else             { B = wvh; Ch = vh; nb = 16; ldc = DIM;  }
    if ((int)blockIdx.x >= nb) return;

    hgemm_core<2>(xh, B, Ch, blockIdx.y * 128, blockIdx.x * 128,
                  DIM, DIM, DIM, ldc);
}

// ---------------------------------------------------------------------------
// fused flash attention: scores + causal online-softmax + PV in one kernel.
// grid (16 m-blocks, 16 heads), 256 threads, 1 CTA/SM.
// Each warp owns 16 q-rows; Q frags resident in regs; K/V streamed in
// t-blocks of 64 through a 3-stage cp.async pipeline.
// ---------------------------------------------------------------------------
__global__ void __launch_bounds__(256, 1)
flash_attn(const __half* __restrict__ Qg, const __half* __restrict__ Kg,
           const __half* __restrict__ Vt, __half* __restrict__ Og,
           float scale)
{
    constexpr int QROW = 400, KROW = 400, VROW = 144;
    constexpr int KOFF  = 128 * QROW;           // 51200
    constexpr int KTILE = TBLK * KROW;          // 25600
    constexpr int VOFF  = KOFF + 3 * KTILE;     // 128000
    constexpr int VTILE = 128 * VROW;           // 18432

    extern __shared__ __align__(1024) char smem[];
    const uint32_t sb = s2u(smem);

    const int m0 = blockIdx.x * 128;
    const int h  = blockIdx.y;
    const int tid = threadIdx.x;
    const int w = tid >> 5, l = tid & 31;

    const __half* Q = Qg + h * HD;                       // row stride QKLD
    const __half* K = Kg + h * HD;
    const __half* V = Vt + (long long)h * VD * SEQ;      // row stride SEQ

    const int nst = (m0 >> 6) + 2;   // t-blocks of 64, covering t <= m0+127

    auto load_q = [&]() {
        #pragma unroll
        for (int i = 0; i < 12; i++) {       // 128 rows x 24 16B-chunks
            int c = tid + (i << 8);
            int row = c / 24, cb = (c % 24) << 4;
            CPA16(sb + row * QROW + cb,
                  (const char*)(Q + (long long)(m0 + row) * QKLD) + cb);
        }
    };
    auto load_stage = [&](int s, int buf) {
        int t0 = s << 6;
        #pragma unroll
        for (int i = 0; i < 6; i++) {        // K: 64 rows x 24 chunks
            int c = tid + (i << 8);
            int row = c / 24, cb = (c % 24) << 4;
            CPA16(sb + KOFF + buf * KTILE + row * KROW + cb,
                  (const char*)(K + (long long)(t0 + row) * QKLD) + cb);
        }
        #pragma unroll
        for (int i = 0; i < 4; i++) {        // V^T: 128 rows x 8 chunks
            int c = tid + (i << 8);
            int row = c >> 3, cb = (c & 7) << 4;
            CPA16(sb + VOFF + buf * VTILE + row * VROW + cb,
                  (const char*)(V + (long long)row * SEQ + t0) + cb);
        }
    };

    load_q();          CPCOMMIT();
    load_stage(0, 0);  CPCOMMIT();
    load_stage(1, 1);  CPCOMMIT();           // nst >= 2 always

    const int arow = (l & 7) + ((l >> 3) & 1) * 8;
    const int akb0 = ((l >> 4) & 1) * 16;
    const int brow = (l & 7) + ((l >> 4) & 1) * 8;
    const int bkb0 = ((l >> 3) & 1) * 16;

    // Q fragments: 12 k-steps x 4 regs (warp's 16 rows x 192)
    CPWAIT2();                  // Q group complete
    __syncthreads();
    uint32_t qf[12][4];
    #pragma unroll
    for (int ks = 0; ks < 12; ks++) {
        int row = w * 16 + arow;
        LDMX4(qf[ks][0], qf[ks][1], qf[ks][2], qf[ks][3],
              sb + row * QROW + ks * 32 + akb0);
    }

    float m1 = -1e30f, m2 = -1e30f, sum1 = 0.f, sum2 = 0.f;
    float oacc[16][4];
    #pragma unroll
    for (int i = 0; i < 16; i++)
        #pragma unroll
        for (int j = 0; j < 4; j++) oacc[i][j] = 0.f;

    const int q1 = m0 + w * 16 + (l >> 2);
    const int q2 = q1 + 8;

    for (int s = 0; s < nst; s++) {
        CPWAIT1();
        __syncthreads();
        if (s + 2 < nst) load_stage(s + 2, (s + 2) % 3);
        CPCOMMIT();

        const uint32_t kb = sb + KOFF + (s % 3) * KTILE;
        const uint32_t vb = sb + VOFF + (s % 3) * VTILE;
        const int t0 = s << 6;

        // ---- S = Q K^T (16 x 64 per warp) ----
        float sacc[8][4];
        #pragma unroll
        for (int i = 0; i < 8; i++)
            #pragma unroll
            for (int j = 0; j < 4; j++) sacc[i][j] = 0.f;
        #pragma unroll
        for (int ks = 0; ks < 12; ks++) {
            uint32_t bf[8][2];
            #pragma unroll
            for (int np = 0; np < 4; np++) {
                int row = np * 16 + brow;
                LDMX4(bf[np*2][0], bf[np*2][1], bf[np*2+1][0], bf[np*2+1][1],
                      kb + row * KROW + ks * 32 + bkb0);
            }
            #pragma unroll
            for (int nt = 0; nt < 8; nt++)
                MMA16816(sacc[nt], qf[ks], bf[nt]);
        }

        // ---- causal mask (partial blocks only) ----
        if (t0 + TBLK - 1 > m0) {
            #pragma unroll
            for (int nt = 0; nt < 8; nt++) {
                int t = t0 + nt * 8 + (l & 3) * 2;
                if (t     > q1) sacc[nt][0] = -1e30f;
                if (t + 1 > q1) sacc[nt][1] = -1e30f;
                if (t     > q2) sacc[nt][2] = -1e30f;
                if (t + 1 > q2) sacc[nt][3] = -1e30f;
            }
        }

        // ---- online softmax update (fp32) ----
        float mt1 = -1e30f, mt2 = -1e30f;
        #pragma unroll
        for (int nt = 0; nt < 8; nt++) {
            mt1 = fmaxf(mt1, fmaxf(sacc[nt][0], sacc[nt][1]));
            mt2 = fmaxf(mt2, fmaxf(sacc[nt][2], sacc[nt][3]));
        }
        mt1 = fmaxf(mt1, __shfl_xor_sync(0xffffffffu, mt1, 1));
        mt1 = fmaxf(mt1, __shfl_xor_sync(0xffffffffu, mt1, 2));
        mt2 = fmaxf(mt2, __shfl_xor_sync(0xffffffffu, mt2, 1));
        mt2 = fmaxf(mt2, __shfl_xor_sync(0xffffffffu, mt2, 2));
        const float m1n = fmaxf(m1, mt1), m2n = fmaxf(m2, mt2);
        const float f1 = __expf((m1 - m1n) * scale);
        const float f2 = __expf((m2 - m2n) * scale);
        m1 = m1n; m2 = m2n;
        #pragma unroll
        for (int nt = 0; nt < 16; nt++) {
            oacc[nt][0] *= f1; oacc[nt][1] *= f1;
            oacc[nt][2] *= f2; oacc[nt][3] *= f2;
        }
        float st1 = 0.f, st2 = 0.f;
        #pragma unroll
        for (int nt = 0; nt < 8; nt++) {
            sacc[nt][0] = __expf((sacc[nt][0] - m1) * scale);
            sacc[nt][1] = __expf((sacc[nt][1] - m1) * scale);
            sacc[nt][2] = __expf((sacc[nt][2] - m2) * scale);
            sacc[nt][3] = __expf((sacc[nt][3] - m2) * scale);
            st1 += sacc[nt][0] + sacc[nt][1];
            st2 += sacc[nt][2] + sacc[nt][3];
        }
        st1 += __shfl_xor_sync(0xffffffffu, st1, 1);
        st1 += __shfl_xor_sync(0xffffffffu, st1, 2);
        st2 += __shfl_xor_sync(0xffffffffu, st2, 1);
        st2 += __shfl_xor_sync(0xffffffffu, st2, 2);
        sum1 = sum1 * f1 + st1;
        sum2 = sum2 * f2 + st2;

        // ---- P fragments: C-frag -> A-frag reinterpretation, fp16 ----
        uint32_t pf[4][4];
        #pragma unroll
        for (int kp = 0; kp < 4; kp++) {
            pf[kp][0] = h2u(__floats2half2_rn(sacc[2*kp][0],   sacc[2*kp][1]));
            pf[kp][1] = h2u(__floats2half2_rn(sacc[2*kp][2],   sacc[2*kp][3]));
            pf[kp][2] = h2u(__floats2half2_rn(sacc[2*kp+1][0], sacc[2*kp+1][1]));
            pf[kp][3] = h2u(__floats2half2_rn(sacc[2*kp+1][2], sacc[2*kp+1][3]));
        }

        // ---- O += P V ----
        #pragma unroll
        for (int kp = 0; kp < 4; kp++) {
            uint32_t bf[16][2];
            #pragma unroll
            for (int np = 0; np < 8; np++) {
                int row = np * 16 + brow;
                LDMX4(bf[np*2][0], bf[np*2][1], bf[np*2+1][0], bf[np*2+1][1],
                      vb + row * VROW + kp * 32 + bkb0);
            }
            #pragma unroll
            for (int nt = 0; nt < 16; nt++)
                MMA16816(oacc[nt], pf[kp], bf[nt]);
        }
    }

    // ---- normalize + write O (fp16) ----
    const float i1 = 1.f / sum1, i2 = 1.f / sum2;
    __half* O1 = Og + (long long)q1 * DIM + h * VD;
    __half* O2 = Og + (long long)q2 * DIM + h * VD;
    #pragma unroll
    for (int nt = 0; nt < 16; nt++) {
        int col = nt * 8 + (l & 3) * 2;
        *(__half2*)(O1 + col) = __floats2half2_rn(oacc[nt][0] * i1, oacc[nt][1] * i1);
        *(__half2*)(O2 + col) = __floats2half2_rn(oacc[nt][2] * i2, oacc[nt][3] * i2);
    }
}

// ---------------------------------------------------------------------------
// fused fp32 -> fp16 (hi only), 16 elements/thread; z selects array
// ---------------------------------------------------------------------------
__global__ void f2h5(const float* __restrict__ x,
                     const float* __restrict__ wq, const float* __restrict__ wk,
                     const float* __restrict__ wv, const float* __restrict__ wo,
                     __half* __restrict__ ox,
                     __half* __restrict__ oq, __half* __restrict__ ok,
                     __half* __restrict__ ov, __half* __restrict__ oo)
{
    const int z = blockIdx.z;
    const float* in; __half* oh; int n;
    if (z == 0)      { in = x;  oh = ox; n = SEQ * DIM; }
    else if (z == 1) { in = wq; oh = oq; n = QKLD * DIM; }
    else if (z == 2) { in = wk; oh = ok; n = QKLD * DIM; }
    else if (z == 3) { in = wv; oh = ov; n = DIM * DIM; }
    else             { in = wo; oh = oo; n = DIM * DIM; }
    int i = (blockIdx.x * 256 + threadIdx.x) * 16;
    if (i >= n) return;
    float4 v0 = *(const float4*)(in + i);
    float4 v1 = *(const float4*)(in + i + 4);
    float4 v2 = *(const float4*)(in + i + 8);
    float4 v3 = *(const float4*)(in + i + 12);
    uint4 o0, o1;
    o0.x = h2u(__floats2half2_rn(v0.x, v0.y));
    o0.y = h2u(__floats2half2_rn(v0.z, v0.w));
    o0.z = h2u(__floats2half2_rn(v1.x, v1.y));
    o0.w = h2u(__floats2half2_rn(v1.z, v1.w));
    o1.x = h2u(__floats2half2_rn(v2.x, v2.y));
    o1.y = h2u(__floats2half2_rn(v2.z, v2.w));
    o1.z = h2u(__floats2half2_rn(v3.x, v3.y));
    o1.w = h2u(__floats2half2_rn(v3.z, v3.w));
    *(uint4*)(oh + i)     = o0;
    *(uint4*)(oh + i + 8) = o1;
}

// ---------------------------------------------------------------------------
// RoPE on pe slices of q, k (hi-only, half2 vectorized)
// ---------------------------------------------------------------------------
__global__ void rope_kernel(__half* __restrict__ Qh, __half* __restrict__ Kh,
                            const float* __restrict__ cosT, const float* __restrict__ sinT)
{
    int idx = blockIdx.x * blockDim.x + threadIdx.x;
    if (idx >= SEQ * NH * (ROPE / 2)) return;
    int i = idx & 31, h = (idx >> 5) & 15, s = idx >> 9;
    float c = cosT[s * 32 + i], sn = sinT[s * 32 + i];
    long long base = (long long)s * QKLD + h * HD + NOPE + 2 * i;
    __half2 q = *(__half2*)(Qh + base);
    float a = __half2float(__low2half(q)), b = __half2float(__high2half(q));
    *(__half2*)(Qh + base) = __floats2half2_rn(a * c - b * sn, a * sn + b * c);
    __half2 k = *(__half2*)(Kh + base);
    a = __half2float(__low2half(k)); b = __half2float(__high2half(k));
    *(__half2*)(Kh + base) = __floats2half2_rn(a * c - b * sn, a * sn + b * c);
}

// ---------------------------------------------------------------------------
__global__ void transpose_h(const __half* __restrict__ in, __half* __restrict__ out)
{
    __shared__ __half t[32][33];
    int x = blockIdx.x * 32 + threadIdx.x;
    int y = blockIdx.y * 32 + threadIdx.y;
    #pragma unroll
    for (int j = 0; j < 32; j += 8)
        t[threadIdx.y + j][threadIdx.x] = in[(long long)(y + j) * DIM + x];
    __syncthreads();
    x = blockIdx.y * 32 + threadIdx.x;
    y = blockIdx.x * 32 + threadIdx.y;
    #pragma unroll
    for (int j = 0; j < 32; j += 8)
        out[(long long)(y + j) * SEQ + x] = t[threadIdx.x][threadIdx.y + j];
}

// ---------------------------------------------------------------------------
extern "C" void kernel_launch(void* const* d_in, const int* in_sizes, int n_in,
                              void* d_out, int out_size)
{
    const float* x  = (const float*)d_in[0];
    const float* wq = (const float*)d_in[1];
    const float* wk = (const float*)d_in[2];
    const float* wv = (const float*)d_in[3];
    const float* wo = (const float*)d_in[4];
    const float* fc = (const float*)d_in[5];
    const float* fs = (const float*)d_in[6];
    float* out = (float*)d_out;

    __half *xh, *wqh, *wkh, *wvh, *woh;
    __half *qh, *kh, *vh, *vth, *oh;
    cudaGetSymbolAddress((void**)&xh, g_xh);
    cudaGetSymbolAddress((void**)&wqh, g_wqh);
    cudaGetSymbolAddress((void**)&wkh, g_wkh);
    cudaGetSymbolAddress((void**)&wvh, g_wvh);
    cudaGetSymbolAddress((void**)&woh, g_woh);
    cudaGetSymbolAddress((void**)&qh, g_qh);
    cudaGetSymbolAddress((void**)&kh, g_kh);
    cudaGetSymbolAddress((void**)&vh, g_vh);
    cudaGetSymbolAddress((void**)&vth, g_vth);
    cudaGetSymbolAddress((void**)&oh, g_oh);

    const int SMEM  = 3 * 36864;   // 110592 (hgemm)
    const int SMEMF = 183296;      // flash_attn: Q 51200 + 3x25600 + 3x18432
    cudaFuncSetAttribute((const void*)hgemm_qkv, cudaFuncAttributeMaxDynamicSharedMemorySize, SMEM);
    cudaFuncSetAttribute((const void*)hgemm<0>,  cudaFuncAttributeMaxDynamicSharedMemorySize, SMEM);
    cudaFuncSetAttribute((const void*)flash_attn, cudaFuncAttributeMaxDynamicSharedMemorySize, SMEMF);

    // fused conversions: x + 4 weights, fp16 hi only
    f2h5<<<dim3(QKLD * DIM / 4096, 1, 5), 256>>>(x, wq, wk, wv, wo,
                                                 xh, wqh, wkh, wvh, woh);

    // fused QKV projections, all fp16 out
    hgemm_qkv<<<dim3(24, 16, 3), 256, SMEM>>>(xh, wqh, wkh, wvh, qh, kh, vh);

    // RoPE (hi-only, half2)
    rope_kernel<<<(SEQ * NH * 32 + 255) / 256, 256>>>(qh, kh, fc, fs);

    // V transpose -> [DIM][SEQ] K-major for flash PV
    transpose_h<<<dim3(64, 64), dim3(32, 8)>>>(vh, vth);

    // fused attention: scores + causal softmax + PV
    flash_attn<<<dim3(16, 16), 256, SMEMF>>>(qh, kh, vth, oh, rsqrtf((float)HD));

    // output projection: fp16 in, fp32 out
    hgemm<0><<<dim3(DIM / 128, SEQ / 128), 256, SMEM>>>(
        oh, woh, out, DIM, DIM, DIM, DIM);
}